// round 7
// baseline (speedup 1.0000x reference)
#include <cuda_runtime.h>
#include <cuda_bf16.h>
#include <cstdint>

#define BATCH 4
#define CH    256
#define CQK   32
#define NN    4096

#define TQ     128
#define TJ     64
#define NTILES (NN / TJ)   // 64

// smem element (bf16) layout: two buffers, each K hi/lo + V^T hi/lo
#define KPAD 40
#define VPAD 72
#define KHe 0
#define KLe 2560                     // 64*40
#define VHe 5120
#define VLe (5120 + 256 * VPAD)      // 5120 + 18432 = 23552
#define BUFE (23552 + 256 * VPAD)    // 41984 elements per buffer
#define SM_BF16_TOTAL (2 * BUFE)     // 83968 el = 167936 B
// byte offsets for cp.async / ldmatrix
#define KH_B 0
#define KL_B 5120
#define VH_B 10240
#define VL_B 47104
#define BUFB 83968

// ---------------- scratch (device globals; no allocation allowed) ----------
__device__ __nv_bfloat16 g_qh[(size_t)BATCH * NN * CQK];
__device__ __nv_bfloat16 g_ql[(size_t)BATCH * NN * CQK];
__device__ __nv_bfloat16 g_kh[(size_t)BATCH * NN * CQK];
__device__ __nv_bfloat16 g_kl[(size_t)BATCH * NN * CQK];
__device__ __nv_bfloat16 g_vth[(size_t)BATCH * CH * NN];   // V^T hi [b][c][n]
__device__ __nv_bfloat16 g_vtl[(size_t)BATCH * CH * NN];   // V^T lo
__device__ float         g_ao [(size_t)BATCH * NN * CH];   // attn out [b][n][c]

// ---------------- helpers ---------------------------------------------------
__device__ __forceinline__ unsigned cvt_bf16x2(float hi, float lo) {
    unsigned r;
    asm("cvt.rn.bf16x2.f32 %0, %1, %2;" : "=r"(r) : "f"(hi), "f"(lo));
    return r;
}
__device__ __forceinline__ float f_lo(unsigned u) { return __uint_as_float(u << 16); }
__device__ __forceinline__ float f_hi(unsigned u) { return __uint_as_float(u & 0xffff0000u); }

__device__ __forceinline__ uint32_t smem_u32(const void* p) {
    uint32_t a;
    asm("{ .reg .u64 t; cvta.to.shared.u64 t, %1; cvt.u32.u64 %0, t; }"
        : "=r"(a) : "l"(p));
    return a;
}
__device__ __forceinline__ void cp16(uint32_t dst, const void* src) {
    asm volatile("cp.async.cg.shared.global [%0], [%1], 16;"
                 :: "r"(dst), "l"(src) : "memory");
}
#define CP_COMMIT() asm volatile("cp.async.commit_group;" ::: "memory")
#define CP_WAIT1()  asm volatile("cp.async.wait_group 1;" ::: "memory")

__device__ __forceinline__ void ldsm4(unsigned& r0, unsigned& r1,
                                      unsigned& r2, unsigned& r3, uint32_t a) {
    asm volatile("ldmatrix.sync.aligned.m8n8.x4.shared.b16 {%0,%1,%2,%3}, [%4];"
                 : "=r"(r0), "=r"(r1), "=r"(r2), "=r"(r3) : "r"(a));
}

// D += A(16x16 bf16, row) * B(16x8 bf16, col)
__device__ __forceinline__ void mma_bf16(float* d, const unsigned* a,
                                         unsigned b0, unsigned b1) {
    asm volatile(
        "mma.sync.aligned.m16n8k16.row.col.f32.bf16.bf16.f32 "
        "{%0,%1,%2,%3}, {%4,%5,%6,%7}, {%8,%9}, {%0,%1,%2,%3};"
        : "+f"(d[0]), "+f"(d[1]), "+f"(d[2]), "+f"(d[3])
        : "r"(a[0]), "r"(a[1]), "r"(a[2]), "r"(a[3]), "r"(b0), "r"(b1));
}

// ============================================================================
// Kernel 1: q/k projection -> bf16 hi/lo
// ============================================================================
__global__ void __launch_bounds__(256)
proj_qk_kernel(const float* __restrict__ x,
               const float* __restrict__ wq, const float* __restrict__ bq,
               const float* __restrict__ wk, const float* __restrict__ bk)
{
    __shared__ __align__(16) float xs[CH * 32];
    const int b   = blockIdx.y;
    const int n0  = blockIdx.x * 32;
    const int tid = threadIdx.x;

    const float* xb = x + (size_t)b * CH * NN + n0;
    for (int idx = tid; idx < CH * 32; idx += 256) {
        int c = idx >> 5, nn = idx & 31;
        xs[c * 32 + nn] = xb[(size_t)c * NN + nn];
    }
    __syncthreads();

    const int ng = tid & 7;
    const int cg = tid >> 3;
    const bool isq = (cg < 16);
    const float* w    = isq ? wq : wk;
    const float* bias = isq ? bq : bk;
    const int d0 = (isq ? cg : cg - 16) * 2;

    float a0[4], a1[4];
    const float b0 = bias[d0], b1 = bias[d0 + 1];
#pragma unroll
    for (int i = 0; i < 4; i++) { a0[i] = b0; a1[i] = b1; }

    const float* w0p = w + (size_t)d0 * CH;
    const float* w1p = w + (size_t)(d0 + 1) * CH;

    for (int c4 = 0; c4 < CH; c4 += 4) {
        float wr0[4], wr1[4];
        *(float4*)wr0 = *(const float4*)(w0p + c4);
        *(float4*)wr1 = *(const float4*)(w1p + c4);
#pragma unroll
        for (int i = 0; i < 4; i++) {
            float xv[4];
            *(float4*)xv = *(const float4*)(xs + (c4 + i) * 32 + ng * 4);
#pragma unroll
            for (int nn = 0; nn < 4; nn++) {
                a0[nn] += wr0[i] * xv[nn];
                a1[nn] += wr1[i] * xv[nn];
            }
        }
    }

    __nv_bfloat16* hq = isq ? g_qh : g_kh;
    __nv_bfloat16* lq = isq ? g_ql : g_kl;
#pragma unroll
    for (int nn = 0; nn < 4; nn++) {
        size_t base = ((size_t)b * NN + n0 + ng * 4 + nn) * CQK + d0;
        unsigned h = cvt_bf16x2(a1[nn], a0[nn]);
        unsigned l = cvt_bf16x2(a1[nn] - f_hi(h), a0[nn] - f_lo(h));
        *(unsigned*)(hq + base) = h;
        *(unsigned*)(lq + base) = l;
    }
}

// ============================================================================
// Kernel 2: v projection -> V^T bf16 hi/lo  [b][c][n]
// ============================================================================
__global__ void __launch_bounds__(256)
proj_v_kernel(const float* __restrict__ x,
              const float* __restrict__ wv, const float* __restrict__ bv)
{
    __shared__ __align__(16) float xs[CH * 32];
    const int b   = blockIdx.y;
    const int n0  = blockIdx.x * 32;
    const int tid = threadIdx.x;

    const float* xb = x + (size_t)b * CH * NN + n0;
    for (int idx = tid; idx < CH * 32; idx += 256) {
        int c = idx >> 5, nn = idx & 31;
        xs[c * 32 + nn] = xb[(size_t)c * NN + nn];
    }
    __syncthreads();

    const int ng = tid & 7;
    const int cg = tid >> 3;

    float acc[8][4];
#pragma unroll
    for (int cc = 0; cc < 8; cc++) {
        float bb = bv[cg * 8 + cc];
#pragma unroll
        for (int i = 0; i < 4; i++) acc[cc][i] = bb;
    }

    for (int c4 = 0; c4 < CH; c4 += 4) {
        float xv[4][4];
#pragma unroll
        for (int i = 0; i < 4; i++)
            *(float4*)xv[i] = *(const float4*)(xs + (c4 + i) * 32 + ng * 4);
#pragma unroll
        for (int cc = 0; cc < 8; cc++) {
            float wr[4];
            *(float4*)wr = *(const float4*)(wv + (size_t)(cg * 8 + cc) * CH + c4);
#pragma unroll
            for (int i = 0; i < 4; i++) {
                acc[cc][0] += wr[i] * xv[i][0];
                acc[cc][1] += wr[i] * xv[i][1];
                acc[cc][2] += wr[i] * xv[i][2];
                acc[cc][3] += wr[i] * xv[i][3];
            }
        }
    }

#pragma unroll
    for (int cc = 0; cc < 8; cc++) {
        int c = cg * 8 + cc;
        size_t base = ((size_t)b * CH + c) * NN + n0 + ng * 4;
        unsigned h0 = cvt_bf16x2(acc[cc][1], acc[cc][0]);
        unsigned h1 = cvt_bf16x2(acc[cc][3], acc[cc][2]);
        unsigned l0 = cvt_bf16x2(acc[cc][1] - f_hi(h0), acc[cc][0] - f_lo(h0));
        unsigned l1 = cvt_bf16x2(acc[cc][3] - f_hi(h1), acc[cc][2] - f_lo(h1));
        *(uint2*)(g_vth + base) = make_uint2(h0, h1);
        *(uint2*)(g_vtl + base) = make_uint2(l0, l1);
    }
}

// ============================================================================
// Kernel 3: HMMA flash attention, cp.async double-buffered, ldmatrix frags.
// ============================================================================
__global__ void __launch_bounds__(256, 1)
attn_kernel()
{
    extern __shared__ __align__(16) __nv_bfloat16 smem[];

    const int tid  = threadIdx.x;
    const int w    = tid >> 5;
    const int lane = tid & 31;
    const int g    = lane >> 2;       // row group 0..7
    const int t    = lane & 3;        // col group 0..3
    const int b    = blockIdx.y;
    const int q0   = blockIdx.x * TQ;
    const int row0 = q0 + w * 16 + g;

    const uint32_t sb = smem_u32(smem);

    // per-thread staging coordinates
    const int kr  = tid >> 2;          // K row 0..63
    const int ks_ = tid & 3;           // K 16B segment 0..3
    const __nv_bfloat16* kh_src0 = g_kh + ((size_t)b * NN + kr) * CQK + ks_ * 8;
    const __nv_bfloat16* kl_src0 = g_kl + ((size_t)b * NN + kr) * CQK + ks_ * 8;
    const uint32_t k_dst_h = (uint32_t)(kr * 80 + ks_ * 16);   // bytes in buffer
    const __nv_bfloat16* vh_src0 = g_vth + ((size_t)b * CH + tid) * NN;
    const __nv_bfloat16* vl_src0 = g_vtl + ((size_t)b * CH + tid) * NN;
    const uint32_t v_dst_row = (uint32_t)(tid * 144);

    // ldmatrix per-lane base offsets (bytes)
    // K: rows = j (8-block row lane&7), cols = d block (lane>>3)*8
    const uint32_t k_lm = (uint32_t)(((lane & 7) * KPAD + (lane >> 3) * 8) * 2);
    // V: rows = c: (lane>>4)*8 + (lane&7); cols = j: ((lane>>3)&1)*8
    const uint32_t v_lm = (uint32_t)((((lane >> 4) * 8 + (lane & 7)) * VPAD
                                      + ((lane >> 3) & 1) * 8) * 2);

    // ---- Q A-fragments (persist) ----
    unsigned qh[2][4], ql[2][4];
    {
        const __nv_bfloat16* qhp = g_qh + (size_t)b * NN * CQK;
        const __nv_bfloat16* qlp = g_ql + (size_t)b * NN * CQK;
#pragma unroll
        for (int kq = 0; kq < 2; kq++) {
            int c0 = kq * 16 + t * 2;
            qh[kq][0] = *(const unsigned*)(qhp + (size_t)row0 * CQK + c0);
            qh[kq][1] = *(const unsigned*)(qhp + (size_t)(row0 + 8) * CQK + c0);
            qh[kq][2] = *(const unsigned*)(qhp + (size_t)row0 * CQK + c0 + 8);
            qh[kq][3] = *(const unsigned*)(qhp + (size_t)(row0 + 8) * CQK + c0 + 8);
            ql[kq][0] = *(const unsigned*)(qlp + (size_t)row0 * CQK + c0);
            ql[kq][1] = *(const unsigned*)(qlp + (size_t)(row0 + 8) * CQK + c0);
            ql[kq][2] = *(const unsigned*)(qlp + (size_t)row0 * CQK + c0 + 8);
            ql[kq][3] = *(const unsigned*)(qlp + (size_t)(row0 + 8) * CQK + c0 + 8);
        }
    }

    // persistent O accumulators
    float o[32][4];
#pragma unroll
    for (int cb = 0; cb < 32; cb++) {
        o[cb][0] = 0.f; o[cb][1] = 0.f; o[cb][2] = 0.f; o[cb][3] = 0.f;
    }
    float rs0 = 0.f, rs1 = 0.f;

    // ---- stage tile 0 into buffer 0 ----
    {
        uint32_t bb = sb;
        cp16(bb + KH_B + k_dst_h, kh_src0);
        cp16(bb + KL_B + k_dst_h, kl_src0);
#pragma unroll
        for (int i = 0; i < 8; i++) {
            cp16(bb + VH_B + v_dst_row + i * 16, vh_src0 + i * 8);
            cp16(bb + VL_B + v_dst_row + i * 16, vl_src0 + i * 8);
        }
    }
    CP_COMMIT();

    for (int tl = 0; tl < NTILES; tl++) {
        // ---- stage tile tl+1 into the other buffer (overlaps compute) ----
        if (tl + 1 < NTILES) {
            const int j1 = (tl + 1) * TJ;
            uint32_t bb = sb + ((tl + 1) & 1) * BUFB;
            cp16(bb + KH_B + k_dst_h, kh_src0 + (size_t)j1 * CQK);
            cp16(bb + KL_B + k_dst_h, kl_src0 + (size_t)j1 * CQK);
#pragma unroll
            for (int i = 0; i < 8; i++) {
                cp16(bb + VH_B + v_dst_row + i * 16, vh_src0 + j1 + i * 8);
                cp16(bb + VL_B + v_dst_row + i * 16, vl_src0 + j1 + i * 8);
            }
        }
        CP_COMMIT();
        CP_WAIT1();
        __syncthreads();

        const uint32_t bb = sb + (tl & 1) * BUFB;
        const uint32_t kh_b = bb + KH_B + k_lm;
        const uint32_t kl_b = bb + KL_B + k_lm;
        const uint32_t vh_b = bb + VH_B + v_lm;
        const uint32_t vl_b = bb + VL_B + v_lm;

#pragma unroll
        for (int kb = 0; kb < 4; kb++) {
            // ---- QK: 4 independent accumulators (jbi x kq) ----
            float s0a[4] = {0.f, 0.f, 0.f, 0.f};
            float s0b[4] = {0.f, 0.f, 0.f, 0.f};
            float s1a[4] = {0.f, 0.f, 0.f, 0.f};
            float s1b[4] = {0.f, 0.f, 0.f, 0.f};
#pragma unroll
            for (int jbi = 0; jbi < 2; jbi++) {
                const uint32_t koff = (uint32_t)((kb * 2 + jbi) * 8 * KPAD * 2);
                unsigned kh0, kh1, kh2, kh3, kl0, kl1, kl2, kl3;
                ldsm4(kh0, kh1, kh2, kh3, kh_b + koff);
                ldsm4(kl0, kl1, kl2, kl3, kl_b + koff);
                float* sa = jbi ? s1a : s0a;
                float* sc = jbi ? s1b : s0b;
                mma_bf16(sa, qh[0], kh0, kh1);
                mma_bf16(sa, qh[0], kl0, kl1);
                mma_bf16(sa, ql[0], kh0, kh1);
                mma_bf16(sc, qh[1], kh2, kh3);
                mma_bf16(sc, qh[1], kl2, kl3);
                mma_bf16(sc, ql[1], kh2, kh3);
            }

            // ---- exp (no max-sub; fp32-safe) ----
            float e00 = __expf(s0a[0] + s0b[0]), e01 = __expf(s0a[1] + s0b[1]);
            float e02 = __expf(s0a[2] + s0b[2]), e03 = __expf(s0a[3] + s0b[3]);
            float e10 = __expf(s1a[0] + s1b[0]), e11 = __expf(s1a[1] + s1b[1]);
            float e12 = __expf(s1a[2] + s1b[2]), e13 = __expf(s1a[3] + s1b[3]);
            rs0 += e00 + e01 + e10 + e11;
            rs1 += e02 + e03 + e12 + e13;

            unsigned pa[4], pl[4];
            pa[0] = cvt_bf16x2(e01, e00);
            pa[1] = cvt_bf16x2(e03, e02);
            pa[2] = cvt_bf16x2(e11, e10);
            pa[3] = cvt_bf16x2(e13, e12);
            pl[0] = cvt_bf16x2(e01 - f_hi(pa[0]), e00 - f_lo(pa[0]));
            pl[1] = cvt_bf16x2(e03 - f_hi(pa[1]), e02 - f_lo(pa[1]));
            pl[2] = cvt_bf16x2(e11 - f_hi(pa[2]), e10 - f_lo(pa[2]));
            pl[3] = cvt_bf16x2(e13 - f_hi(pa[3]), e12 - f_lo(pa[3]));

            // ---- PV: O += Ph*Vh + Ph*Vl + Pl*Vh, ldmatrix.x4 = 2 c-blocks ----
            uint32_t avh = vh_b + (uint32_t)(kb * 16 * 2);
            uint32_t avl = vl_b + (uint32_t)(kb * 16 * 2);
#pragma unroll
            for (int p = 0; p < 16; p++) {
                unsigned vh0a, vh1a, vh0b, vh1b;
                unsigned vl0a, vl1a, vl0b, vl1b;
                ldsm4(vh0a, vh1a, vh0b, vh1b, avh);
                ldsm4(vl0a, vl1a, vl0b, vl1b, avl);
                mma_bf16(o[2 * p],     pa, vh0a, vh1a);
                mma_bf16(o[2 * p],     pa, vl0a, vl1a);
                mma_bf16(o[2 * p],     pl, vh0a, vh1a);
                mma_bf16(o[2 * p + 1], pa, vh0b, vh1b);
                mma_bf16(o[2 * p + 1], pa, vl0b, vl1b);
                mma_bf16(o[2 * p + 1], pl, vh0b, vh1b);
                avh += 16 * VPAD * 2;
                avl += 16 * VPAD * 2;
            }
        }
        __syncthreads();
    }

    // ---- rowsum reduce across the 4 lanes sharing a row ----
    rs0 += __shfl_xor_sync(0xffffffffu, rs0, 1);
    rs0 += __shfl_xor_sync(0xffffffffu, rs0, 2);
    rs1 += __shfl_xor_sync(0xffffffffu, rs1, 1);
    rs1 += __shfl_xor_sync(0xffffffffu, rs1, 2);
    const float inv0 = 1.0f / rs0;
    const float inv1 = 1.0f / rs1;

    float* d0p = g_ao + ((size_t)b * NN + row0) * CH;
    float* d1p = g_ao + ((size_t)b * NN + row0 + 8) * CH;
#pragma unroll
    for (int cb = 0; cb < 32; cb++) {
        *(float2*)(d0p + cb * 8 + t * 2) = make_float2(o[cb][0] * inv0, o[cb][1] * inv0);
        *(float2*)(d1p + cb * 8 + t * 2) = make_float2(o[cb][2] * inv1, o[cb][3] * inv1);
    }
}

// ============================================================================
// Kernel 4: output projection + residual.
// ============================================================================
__global__ void __launch_bounds__(256)
final_kernel(const float* __restrict__ x,
             const float* __restrict__ wg, const float* __restrict__ bg,
             float* __restrict__ y)
{
    __shared__ __align__(16) float as[CH * 36];
    const int b   = blockIdx.y;
    const int n0  = blockIdx.x * 32;
    const int tid = threadIdx.x;

    const float* aob = g_ao + ((size_t)b * NN + n0) * CH;
    for (int idx = tid; idx < 32 * CH; idx += 256) {
        int nn = idx >> 8, c = idx & 255;
        as[c * 36 + nn] = aob[(size_t)nn * CH + c];
    }
    __syncthreads();

    const int ng = tid & 7;
    const int cg = tid >> 3;

    float acc[8][4];
#pragma unroll
    for (int cc = 0; cc < 8; cc++) {
        float bb = bg[cg * 8 + cc];
#pragma unroll
        for (int i = 0; i < 4; i++) acc[cc][i] = bb;
    }

    for (int c4 = 0; c4 < CH; c4 += 4) {
        float xv[4][4];
#pragma unroll
        for (int i = 0; i < 4; i++)
            *(float4*)xv[i] = *(const float4*)(as + (c4 + i) * 36 + ng * 4);
#pragma unroll
        for (int cc = 0; cc < 8; cc++) {
            float wr[4];
            *(float4*)wr = *(const float4*)(wg + (size_t)(cg * 8 + cc) * CH + c4);
#pragma unroll
            for (int i = 0; i < 4; i++) {
                acc[cc][0] += wr[i] * xv[i][0];
                acc[cc][1] += wr[i] * xv[i][1];
                acc[cc][2] += wr[i] * xv[i][2];
                acc[cc][3] += wr[i] * xv[i][3];
            }
        }
    }

    const float* xb = x + (size_t)b * CH * NN + n0 + ng * 4;
    float*       yb = y + (size_t)b * CH * NN + n0 + ng * 4;
#pragma unroll
    for (int cc = 0; cc < 8; cc++) {
        int c = cg * 8 + cc;
        float4 xr = *(const float4*)(xb + (size_t)c * NN);
        *(float4*)(yb + (size_t)c * NN) =
            make_float4(xr.x + acc[cc][0], xr.y + acc[cc][1],
                        xr.z + acc[cc][2], xr.w + acc[cc][3]);
    }
}

// ============================================================================
extern "C" void kernel_launch(void* const* d_in, const int* in_sizes, int n_in,
                              void* d_out, int out_size)
{
    const float* x  = (const float*)d_in[0];
    const float* wq = (const float*)d_in[1];
    const float* bq = (const float*)d_in[2];
    const float* wk = (const float*)d_in[3];
    const float* bk = (const float*)d_in[4];
    const float* wv = (const float*)d_in[5];
    const float* bv = (const float*)d_in[6];
    const float* wg = (const float*)d_in[7];
    const float* bg = (const float*)d_in[8];
    float* y = (float*)d_out;

    const int attn_smem = SM_BF16_TOTAL * 2;   // bytes
    cudaFuncSetAttribute(attn_kernel,
                         cudaFuncAttributeMaxDynamicSharedMemorySize, attn_smem);

    proj_qk_kernel<<<dim3(NN / 32, BATCH), 256>>>(x, wq, bq, wk, bk);
    proj_v_kernel <<<dim3(NN / 32, BATCH), 256>>>(x, wv, bv);
    attn_kernel   <<<dim3(NN / TQ, BATCH), 256, attn_smem>>>();
    final_kernel  <<<dim3(NN / 32, BATCH), 256>>>(x, wg, bg, y);
}

// round 8
// speedup vs baseline: 1.2708x; 1.2708x over previous
#include <cuda_runtime.h>
#include <cuda_bf16.h>
#include <cstdint>

#define BATCH 4
#define CH    256
#define CQK   32
#define NN    4096

#define TQ     128
#define TJ     64
#define NTILES (NN / TJ)   // 64

// ---- SMEM byte layout: [mbar pad 1024][buf0][buf1] ----
#define KPAD    40
#define K_BYTES (64 * KPAD * 2)          // 5120 per half (hi or lo)
#define V_BYTES (2 * 256 * 64 * 2)       // 65536 (hi+lo packed swizzled tile)
#define BUF_B   (2 * K_BYTES + V_BYTES)  // 75776
#define SM_MB0  0
#define SM_MB1  8
#define SM_BUF  1024
#define KH_OFF  0
#define KL_OFF  K_BYTES
#define V_OFF   (2 * K_BYTES)            // 10240
#define SM_TOTAL (SM_BUF + 2 * BUF_B)    // 152576

// ---------------- scratch (device globals; no allocation allowed) ----------
__device__ __nv_bfloat16 g_qh[(size_t)BATCH * NN * CQK];
__device__ __nv_bfloat16 g_ql[(size_t)BATCH * NN * CQK];
__device__ __nv_bfloat16 g_kh[(size_t)BATCH * NN * CQK];
__device__ __nv_bfloat16 g_kl[(size_t)BATCH * NN * CQK];
// V^T, tile-contiguous + swizzled: [b][tile][hi/lo][c:256][j:64]
__device__ __align__(128) __nv_bfloat16 g_v[(size_t)BATCH * NTILES * 2 * 256 * 64];
__device__ float g_ao[(size_t)BATCH * NN * CH];   // attn out [b][n][c]

// ---------------- helpers ---------------------------------------------------
__device__ __forceinline__ unsigned cvt_bf16x2(float hi, float lo) {
    unsigned r;
    asm("cvt.rn.bf16x2.f32 %0, %1, %2;" : "=r"(r) : "f"(hi), "f"(lo));
    return r;
}
__device__ __forceinline__ float f_lo(unsigned u) { return __uint_as_float(u << 16); }
__device__ __forceinline__ float f_hi(unsigned u) { return __uint_as_float(u & 0xffff0000u); }

__device__ __forceinline__ uint32_t smem_u32(const void* p) {
    uint32_t a;
    asm("{ .reg .u64 t; cvta.to.shared.u64 t, %1; cvt.u32.u64 %0, t; }"
        : "=r"(a) : "l"(p));
    return a;
}
__device__ __forceinline__ void cp16(uint32_t dst, const void* src) {
    asm volatile("cp.async.cg.shared.global [%0], [%1], 16;"
                 :: "r"(dst), "l"(src) : "memory");
}
#define CP_COMMIT() asm volatile("cp.async.commit_group;" ::: "memory")
#define CP_WAIT1()  asm volatile("cp.async.wait_group 1;" ::: "memory")

#define MBAR_INIT(addr, cnt) \
    asm volatile("mbarrier.init.shared.b64 [%0], %1;" :: "r"(addr), "r"(cnt) : "memory")
#define MBAR_EXPECT_TX(addr, bytes) \
    asm volatile("mbarrier.arrive.expect_tx.shared.b64 _, [%0], %1;" \
                 :: "r"(addr), "r"(bytes) : "memory")

__device__ __forceinline__ void mbar_wait(uint32_t addr, uint32_t parity) {
    asm volatile(
        "{\n\t.reg .pred P;\n\t"
        "WL_%=:\n\t"
        "mbarrier.try_wait.parity.acquire.cta.shared::cta.b64 P, [%0], %1, 0x989680;\n\t"
        "@P bra WD_%=;\n\t"
        "bra WL_%=;\n\t"
        "WD_%=:\n\t}"
        :: "r"(addr), "r"(parity) : "memory");
}
__device__ __forceinline__ void bulk_g2s(uint32_t dst, const void* src,
                                         uint32_t bytes, uint32_t mbar) {
    asm volatile(
        "cp.async.bulk.shared::cluster.global.mbarrier::complete_tx::bytes "
        "[%0], [%1], %2, [%3];"
        :: "r"(dst), "l"(src), "r"(bytes), "r"(mbar) : "memory");
}

__device__ __forceinline__ void ldsm4(unsigned& r0, unsigned& r1,
                                      unsigned& r2, unsigned& r3, uint32_t a) {
    asm volatile("ldmatrix.sync.aligned.m8n8.x4.shared.b16 {%0,%1,%2,%3}, [%4];"
                 : "=r"(r0), "=r"(r1), "=r"(r2), "=r"(r3) : "r"(a));
}

// D += A(16x16 bf16, row) * B(16x8 bf16, col)
__device__ __forceinline__ void mma_bf16(float* d, const unsigned* a,
                                         unsigned b0, unsigned b1) {
    asm volatile(
        "mma.sync.aligned.m16n8k16.row.col.f32.bf16.bf16.f32 "
        "{%0,%1,%2,%3}, {%4,%5,%6,%7}, {%8,%9}, {%0,%1,%2,%3};"
        : "+f"(d[0]), "+f"(d[1]), "+f"(d[2]), "+f"(d[3])
        : "r"(a[0]), "r"(a[1]), "r"(a[2]), "r"(a[3]), "r"(b0), "r"(b1));
}

// ============================================================================
// Kernel 1: q/k projection -> bf16 hi/lo
// ============================================================================
__global__ void __launch_bounds__(256)
proj_qk_kernel(const float* __restrict__ x,
               const float* __restrict__ wq, const float* __restrict__ bq,
               const float* __restrict__ wk, const float* __restrict__ bk)
{
    __shared__ __align__(16) float xs[CH * 32];
    const int b   = blockIdx.y;
    const int n0  = blockIdx.x * 32;
    const int tid = threadIdx.x;

    const float* xb = x + (size_t)b * CH * NN + n0;
    for (int idx = tid; idx < CH * 32; idx += 256) {
        int c = idx >> 5, nn = idx & 31;
        xs[c * 32 + nn] = xb[(size_t)c * NN + nn];
    }
    __syncthreads();

    const int ng = tid & 7;
    const int cg = tid >> 3;
    const bool isq = (cg < 16);
    const float* w    = isq ? wq : wk;
    const float* bias = isq ? bq : bk;
    const int d0 = (isq ? cg : cg - 16) * 2;

    float a0[4], a1[4];
    const float b0 = bias[d0], b1 = bias[d0 + 1];
#pragma unroll
    for (int i = 0; i < 4; i++) { a0[i] = b0; a1[i] = b1; }

    const float* w0p = w + (size_t)d0 * CH;
    const float* w1p = w + (size_t)(d0 + 1) * CH;

    for (int c4 = 0; c4 < CH; c4 += 4) {
        float wr0[4], wr1[4];
        *(float4*)wr0 = *(const float4*)(w0p + c4);
        *(float4*)wr1 = *(const float4*)(w1p + c4);
#pragma unroll
        for (int i = 0; i < 4; i++) {
            float xv[4];
            *(float4*)xv = *(const float4*)(xs + (c4 + i) * 32 + ng * 4);
#pragma unroll
            for (int nn = 0; nn < 4; nn++) {
                a0[nn] += wr0[i] * xv[nn];
                a1[nn] += wr1[i] * xv[nn];
            }
        }
    }

    __nv_bfloat16* hq = isq ? g_qh : g_kh;
    __nv_bfloat16* lq = isq ? g_ql : g_kl;
#pragma unroll
    for (int nn = 0; nn < 4; nn++) {
        size_t base = ((size_t)b * NN + n0 + ng * 4 + nn) * CQK + d0;
        unsigned h = cvt_bf16x2(a1[nn], a0[nn]);
        unsigned l = cvt_bf16x2(a1[nn] - f_hi(h), a0[nn] - f_lo(h));
        *(unsigned*)(hq + base) = h;
        *(unsigned*)(lq + base) = l;
    }
}

// ============================================================================
// Kernel 2: v projection -> tile-contiguous swizzled V^T hi/lo
// element offset within tile: c*64 + ((j>>3) ^ (c&7))*8 + (j&7)
// ============================================================================
__global__ void __launch_bounds__(256)
proj_v_kernel(const float* __restrict__ x,
              const float* __restrict__ wv, const float* __restrict__ bv)
{
    __shared__ __align__(16) float xs[CH * 32];
    const int b   = blockIdx.y;
    const int n0  = blockIdx.x * 32;
    const int tid = threadIdx.x;

    const float* xb = x + (size_t)b * CH * NN + n0;
    for (int idx = tid; idx < CH * 32; idx += 256) {
        int c = idx >> 5, nn = idx & 31;
        xs[c * 32 + nn] = xb[(size_t)c * NN + nn];
    }
    __syncthreads();

    const int ng = tid & 7;
    const int cg = tid >> 3;

    float acc[8][4];
#pragma unroll
    for (int cc = 0; cc < 8; cc++) {
        float bb = bv[cg * 8 + cc];
#pragma unroll
        for (int i = 0; i < 4; i++) acc[cc][i] = bb;
    }

    for (int c4 = 0; c4 < CH; c4 += 4) {
        float xv[4][4];
#pragma unroll
        for (int i = 0; i < 4; i++)
            *(float4*)xv[i] = *(const float4*)(xs + (c4 + i) * 32 + ng * 4);
#pragma unroll
        for (int cc = 0; cc < 8; cc++) {
            float wr[4];
            *(float4*)wr = *(const float4*)(wv + (size_t)(cg * 8 + cc) * CH + c4);
#pragma unroll
            for (int i = 0; i < 4; i++) {
                acc[cc][0] += wr[i] * xv[i][0];
                acc[cc][1] += wr[i] * xv[i][1];
                acc[cc][2] += wr[i] * xv[i][2];
                acc[cc][3] += wr[i] * xv[i][3];
            }
        }
    }

    const int tile = n0 >> 6;
    const int jt   = (n0 & 63) + ng * 4;            // j within tile, 8B-chunk safe
    const size_t tbase = ((size_t)b * NTILES + tile) * (2 * 256 * 64);
#pragma unroll
    for (int cc = 0; cc < 8; cc++) {
        int c = cg * 8 + cc;
        int off = c * 64 + (((jt >> 3) ^ (c & 7)) << 3) + (jt & 7);
        unsigned h0 = cvt_bf16x2(acc[cc][1], acc[cc][0]);
        unsigned h1 = cvt_bf16x2(acc[cc][3], acc[cc][2]);
        unsigned l0 = cvt_bf16x2(acc[cc][1] - f_hi(h0), acc[cc][0] - f_lo(h0));
        unsigned l1 = cvt_bf16x2(acc[cc][3] - f_hi(h1), acc[cc][2] - f_lo(h1));
        *(uint2*)(g_v + tbase + off)             = make_uint2(h0, h1);
        *(uint2*)(g_v + tbase + 16384 + off)     = make_uint2(l0, l1);
    }
}

// ============================================================================
// Kernel 3: HMMA flash attention; V staged via cp.async.bulk + mbarrier,
// K via cp.async; double-buffered; ldmatrix fragments.
// ============================================================================
__global__ void __launch_bounds__(256, 1)
attn_kernel()
{
    extern __shared__ __align__(1024) char smem[];

    const int tid  = threadIdx.x;
    const int w    = tid >> 5;
    const int lane = tid & 31;
    const int g    = lane >> 2;
    const int t    = lane & 3;
    const int b    = blockIdx.y;
    const int q0   = blockIdx.x * TQ;
    const int row0 = q0 + w * 16 + g;

    const uint32_t sb = smem_u32(smem);
    const uint32_t mb0 = sb + SM_MB0;
    const uint32_t mb1 = sb + SM_MB1;

    if (tid == 0) { MBAR_INIT(mb0, 1); MBAR_INIT(mb1, 1); }
    __syncthreads();

    // K staging coords (cp.async, padded)
    const int kr  = tid >> 2;
    const int ks_ = tid & 3;
    const __nv_bfloat16* kh_src0 = g_kh + ((size_t)b * NN + kr) * CQK + ks_ * 8;
    const __nv_bfloat16* kl_src0 = g_kl + ((size_t)b * NN + kr) * CQK + ks_ * 8;
    const uint32_t k_dst = (uint32_t)(kr * 80 + ks_ * 16);

    // V bulk source
    const __nv_bfloat16* v_src0 = g_v + (size_t)b * NTILES * (2 * 256 * 64);

    // ldmatrix per-lane offsets
    const uint32_t k_lm = (uint32_t)(((lane & 7) * KPAD + (lane >> 3) * 8) * 2);
    const int vm = lane >> 3;          // matrix id 0..3
    const int vr = lane & 7;           // row-in-matrix
    const uint32_t v_row = (uint32_t)(((vm >> 1) * 8 + vr) * 128);  // c-part bytes

    // ---- Q A-fragments (persist) ----
    unsigned qh[2][4], ql[2][4];
    {
        const __nv_bfloat16* qhp = g_qh + (size_t)b * NN * CQK;
        const __nv_bfloat16* qlp = g_ql + (size_t)b * NN * CQK;
#pragma unroll
        for (int kq = 0; kq < 2; kq++) {
            int c0 = kq * 16 + t * 2;
            qh[kq][0] = *(const unsigned*)(qhp + (size_t)row0 * CQK + c0);
            qh[kq][1] = *(const unsigned*)(qhp + (size_t)(row0 + 8) * CQK + c0);
            qh[kq][2] = *(const unsigned*)(qhp + (size_t)row0 * CQK + c0 + 8);
            qh[kq][3] = *(const unsigned*)(qhp + (size_t)(row0 + 8) * CQK + c0 + 8);
            ql[kq][0] = *(const unsigned*)(qlp + (size_t)row0 * CQK + c0);
            ql[kq][1] = *(const unsigned*)(qlp + (size_t)(row0 + 8) * CQK + c0);
            ql[kq][2] = *(const unsigned*)(qlp + (size_t)row0 * CQK + c0 + 8);
            ql[kq][3] = *(const unsigned*)(qlp + (size_t)(row0 + 8) * CQK + c0 + 8);
        }
    }

    float o[32][4];
#pragma unroll
    for (int cb = 0; cb < 32; cb++) {
        o[cb][0] = 0.f; o[cb][1] = 0.f; o[cb][2] = 0.f; o[cb][3] = 0.f;
    }
    float rs0 = 0.f, rs1 = 0.f;

    // ---- stage tile 0 ----
    {
        uint32_t bb = sb + SM_BUF;
        cp16(bb + KH_OFF + k_dst, kh_src0);
        cp16(bb + KL_OFF + k_dst, kl_src0);
        if (tid == 0) {
            MBAR_EXPECT_TX(mb0, V_BYTES);
            bulk_g2s(bb + V_OFF, v_src0, V_BYTES, mb0);
        }
    }
    CP_COMMIT();

    for (int tl = 0; tl < NTILES; tl++) {
        if (tl + 1 < NTILES) {
            const int j1 = (tl + 1) * TJ;
            uint32_t bb = sb + SM_BUF + ((tl + 1) & 1) * BUF_B;
            cp16(bb + KH_OFF + k_dst, kh_src0 + (size_t)j1 * CQK);
            cp16(bb + KL_OFF + k_dst, kl_src0 + (size_t)j1 * CQK);
            if (tid == 0) {
                uint32_t mb = ((tl + 1) & 1) ? mb1 : mb0;
                MBAR_EXPECT_TX(mb, V_BYTES);
                bulk_g2s(bb + V_OFF, v_src0 + (size_t)(tl + 1) * (2 * 256 * 64),
                         V_BYTES, mb);
            }
        }
        CP_COMMIT();
        CP_WAIT1();                                   // K of tile tl resident
        mbar_wait((tl & 1) ? mb1 : mb0, (tl >> 1) & 1);   // V of tile tl
        __syncthreads();

        const uint32_t bb  = sb + SM_BUF + (tl & 1) * BUF_B;
        const uint32_t khb = bb + KH_OFF + k_lm;
        const uint32_t klb = bb + KL_OFF + k_lm;
        const uint32_t vhb = bb + V_OFF + v_row;
        const uint32_t vlb = vhb + 32768;

#pragma unroll
        for (int kb = 0; kb < 4; kb++) {
            // swizzled V chunk offset for this kb (per-lane)
            const uint32_t vsw = (uint32_t)(((kb * 2 + (vm & 1)) ^ vr) * 16);

            // ---- QK: 4 independent accumulators ----
            float s0a[4] = {0.f, 0.f, 0.f, 0.f};
            float s0b[4] = {0.f, 0.f, 0.f, 0.f};
            float s1a[4] = {0.f, 0.f, 0.f, 0.f};
            float s1b[4] = {0.f, 0.f, 0.f, 0.f};
#pragma unroll
            for (int jbi = 0; jbi < 2; jbi++) {
                const uint32_t koff = (uint32_t)((kb * 2 + jbi) * 8 * KPAD * 2);
                unsigned kh0, kh1, kh2, kh3, kl0, kl1, kl2, kl3;
                ldsm4(kh0, kh1, kh2, kh3, khb + koff);
                ldsm4(kl0, kl1, kl2, kl3, klb + koff);
                float* sa = jbi ? s1a : s0a;
                float* sc = jbi ? s1b : s0b;
                mma_bf16(sa, qh[0], kh0, kh1);
                mma_bf16(sa, qh[0], kl0, kl1);
                mma_bf16(sa, ql[0], kh0, kh1);
                mma_bf16(sc, qh[1], kh2, kh3);
                mma_bf16(sc, qh[1], kl2, kl3);
                mma_bf16(sc, ql[1], kh2, kh3);
            }

            float e00 = __expf(s0a[0] + s0b[0]), e01 = __expf(s0a[1] + s0b[1]);
            float e02 = __expf(s0a[2] + s0b[2]), e03 = __expf(s0a[3] + s0b[3]);
            float e10 = __expf(s1a[0] + s1b[0]), e11 = __expf(s1a[1] + s1b[1]);
            float e12 = __expf(s1a[2] + s1b[2]), e13 = __expf(s1a[3] + s1b[3]);
            rs0 += e00 + e01 + e10 + e11;
            rs1 += e02 + e03 + e12 + e13;

            unsigned pa[4], pl[4];
            pa[0] = cvt_bf16x2(e01, e00);
            pa[1] = cvt_bf16x2(e03, e02);
            pa[2] = cvt_bf16x2(e11, e10);
            pa[3] = cvt_bf16x2(e13, e12);
            pl[0] = cvt_bf16x2(e01 - f_hi(pa[0]), e00 - f_lo(pa[0]));
            pl[1] = cvt_bf16x2(e03 - f_hi(pa[1]), e02 - f_lo(pa[1]));
            pl[2] = cvt_bf16x2(e11 - f_hi(pa[2]), e10 - f_lo(pa[2]));
            pl[3] = cvt_bf16x2(e13 - f_hi(pa[3]), e12 - f_lo(pa[3]));

            // ---- PV over 16 c-pairs; ldmatrix.x4 = 2 c-blocks ----
            uint32_t avh = vhb + vsw;
            uint32_t avl = vlb + vsw;
#pragma unroll
            for (int p = 0; p < 16; p++) {
                unsigned vh0a, vh1a, vh0b, vh1b;
                unsigned vl0a, vl1a, vl0b, vl1b;
                ldsm4(vh0a, vh1a, vh0b, vh1b, avh);
                ldsm4(vl0a, vl1a, vl0b, vl1b, avl);
                mma_bf16(o[2 * p],     pa, vh0a, vh1a);
                mma_bf16(o[2 * p],     pa, vl0a, vl1a);
                mma_bf16(o[2 * p],     pl, vh0a, vh1a);
                mma_bf16(o[2 * p + 1], pa, vh0b, vh1b);
                mma_bf16(o[2 * p + 1], pa, vl0b, vl1b);
                mma_bf16(o[2 * p + 1], pl, vh0b, vh1b);
                avh += 16 * 128;
                avl += 16 * 128;
            }
        }
        __syncthreads();
    }

    rs0 += __shfl_xor_sync(0xffffffffu, rs0, 1);
    rs0 += __shfl_xor_sync(0xffffffffu, rs0, 2);
    rs1 += __shfl_xor_sync(0xffffffffu, rs1, 1);
    rs1 += __shfl_xor_sync(0xffffffffu, rs1, 2);
    const float inv0 = 1.0f / rs0;
    const float inv1 = 1.0f / rs1;

    float* d0p = g_ao + ((size_t)b * NN + row0) * CH;
    float* d1p = g_ao + ((size_t)b * NN + row0 + 8) * CH;
#pragma unroll
    for (int cb = 0; cb < 32; cb++) {
        *(float2*)(d0p + cb * 8 + t * 2) = make_float2(o[cb][0] * inv0, o[cb][1] * inv0);
        *(float2*)(d1p + cb * 8 + t * 2) = make_float2(o[cb][2] * inv1, o[cb][3] * inv1);
    }
}

// ============================================================================
// Kernel 4: output projection + residual.
// ============================================================================
__global__ void __launch_bounds__(256)
final_kernel(const float* __restrict__ x,
             const float* __restrict__ wg, const float* __restrict__ bg,
             float* __restrict__ y)
{
    __shared__ __align__(16) float as[CH * 36];
    const int b   = blockIdx.y;
    const int n0  = blockIdx.x * 32;
    const int tid = threadIdx.x;

    const float* aob = g_ao + ((size_t)b * NN + n0) * CH;
    for (int idx = tid; idx < 32 * CH; idx += 256) {
        int nn = idx >> 8, c = idx & 255;
        as[c * 36 + nn] = aob[(size_t)nn * CH + c];
    }
    __syncthreads();

    const int ng = tid & 7;
    const int cg = tid >> 3;

    float acc[8][4];
#pragma unroll
    for (int cc = 0; cc < 8; cc++) {
        float bb = bg[cg * 8 + cc];
#pragma unroll
        for (int i = 0; i < 4; i++) acc[cc][i] = bb;
    }

    for (int c4 = 0; c4 < CH; c4 += 4) {
        float xv[4][4];
#pragma unroll
        for (int i = 0; i < 4; i++)
            *(float4*)xv[i] = *(const float4*)(as + (c4 + i) * 36 + ng * 4);
#pragma unroll
        for (int cc = 0; cc < 8; cc++) {
            float wr[4];
            *(float4*)wr = *(const float4*)(wg + (size_t)(cg * 8 + cc) * CH + c4);
#pragma unroll
            for (int i = 0; i < 4; i++) {
                acc[cc][0] += wr[i] * xv[i][0];
                acc[cc][1] += wr[i] * xv[i][1];
                acc[cc][2] += wr[i] * xv[i][2];
                acc[cc][3] += wr[i] * xv[i][3];
            }
        }
    }

    const float* xb = x + (size_t)b * CH * NN + n0 + ng * 4;
    float*       yb = y + (size_t)b * CH * NN + n0 + ng * 4;
#pragma unroll
    for (int cc = 0; cc < 8; cc++) {
        int c = cg * 8 + cc;
        float4 xr = *(const float4*)(xb + (size_t)c * NN);
        *(float4*)(yb + (size_t)c * NN) =
            make_float4(xr.x + acc[cc][0], xr.y + acc[cc][1],
                        xr.z + acc[cc][2], xr.w + acc[cc][3]);
    }
}

// ============================================================================
extern "C" void kernel_launch(void* const* d_in, const int* in_sizes, int n_in,
                              void* d_out, int out_size)
{
    const float* x  = (const float*)d_in[0];
    const float* wq = (const float*)d_in[1];
    const float* bq = (const float*)d_in[2];
    const float* wk = (const float*)d_in[3];
    const float* bk = (const float*)d_in[4];
    const float* wv = (const float*)d_in[5];
    const float* bv = (const float*)d_in[6];
    const float* wg = (const float*)d_in[7];
    const float* bg = (const float*)d_in[8];
    float* y = (float*)d_out;

    cudaFuncSetAttribute(attn_kernel,
                         cudaFuncAttributeMaxDynamicSharedMemorySize, SM_TOTAL);

    proj_qk_kernel<<<dim3(NN / 32, BATCH), 256>>>(x, wq, bq, wk, bk);
    proj_v_kernel <<<dim3(NN / 32, BATCH), 256>>>(x, wv, bv);
    attn_kernel   <<<dim3(NN / TQ, BATCH), 256, SM_TOTAL>>>();
    final_kernel  <<<dim3(NN / 32, BATCH), 256>>>(x, wg, bg, y);
}

// round 9
// speedup vs baseline: 1.5459x; 1.2165x over previous
#include <cuda_runtime.h>
#include <cuda_bf16.h>
#include <cstdint>

#define BATCH 4
#define CH    256
#define CQK   32
#define NN    4096

#define TQ     128
#define TJ     64
#define NTILES (NN / TJ)   // 64

// ---- unified KV tile (bf16 elements): [KH 64x40][KL 64x40][VH 256x64][VL 256x64]
#define KPAD       40
#define KV_TILE_EL 37888                  // 2*2560 + 2*16384
#define KV_TILE_B  75776
#define KH_OFF     0                      // bytes
#define KL_OFF     5120
#define V_OFF      10240
// attn SMEM: [mbar pad 1024][buf0][buf1]
#define SM_MB0  0
#define SM_MB1  8
#define SM_BUF  1024
#define SM_TOTAL (SM_BUF + 2 * KV_TILE_B)   // 152576

// final SMEM: [mbar pad 1024][ao_hi 64KB][ao_lo 64KB]
#define FIN_SM_TOTAL (1024 + 2 * 65536)

// ---------------- scratch (device globals; no allocation allowed) ----------
__device__ __nv_bfloat16 g_qh[(size_t)BATCH * NN * CQK];
__device__ __nv_bfloat16 g_ql[(size_t)BATCH * NN * CQK];
__device__ __align__(128) __nv_bfloat16 g_kv[(size_t)BATCH * NTILES * KV_TILE_EL];
__device__ __align__(128) __nv_bfloat16 g_aoh[(size_t)BATCH * NN * CH];  // swizzled
__device__ __align__(128) __nv_bfloat16 g_aol[(size_t)BATCH * NN * CH];
__device__ __nv_bfloat16 g_wgh[CH * CH];
__device__ __nv_bfloat16 g_wgl[CH * CH];

// ---------------- helpers ---------------------------------------------------
__device__ __forceinline__ unsigned cvt_bf16x2(float hi, float lo) {
    unsigned r;
    asm("cvt.rn.bf16x2.f32 %0, %1, %2;" : "=r"(r) : "f"(hi), "f"(lo));
    return r;
}
__device__ __forceinline__ float f_lo(unsigned u) { return __uint_as_float(u << 16); }
__device__ __forceinline__ float f_hi(unsigned u) { return __uint_as_float(u & 0xffff0000u); }

__device__ __forceinline__ uint32_t smem_u32(const void* p) {
    uint32_t a;
    asm("{ .reg .u64 t; cvta.to.shared.u64 t, %1; cvt.u32.u64 %0, t; }"
        : "=r"(a) : "l"(p));
    return a;
}

#define MBAR_INIT(addr, cnt) \
    asm volatile("mbarrier.init.shared.b64 [%0], %1;" :: "r"(addr), "r"(cnt) : "memory")
#define MBAR_EXPECT_TX(addr, bytes) \
    asm volatile("mbarrier.arrive.expect_tx.shared.b64 _, [%0], %1;" \
                 :: "r"(addr), "r"(bytes) : "memory")

__device__ __forceinline__ void mbar_wait(uint32_t addr, uint32_t parity) {
    asm volatile(
        "{\n\t.reg .pred P;\n\t"
        "WL_%=:\n\t"
        "mbarrier.try_wait.parity.acquire.cta.shared::cta.b64 P, [%0], %1, 0x989680;\n\t"
        "@P bra WD_%=;\n\t"
        "bra WL_%=;\n\t"
        "WD_%=:\n\t}"
        :: "r"(addr), "r"(parity) : "memory");
}
__device__ __forceinline__ void bulk_g2s(uint32_t dst, const void* src,
                                         uint32_t bytes, uint32_t mbar) {
    asm volatile(
        "cp.async.bulk.shared::cluster.global.mbarrier::complete_tx::bytes "
        "[%0], [%1], %2, [%3];"
        :: "r"(dst), "l"(src), "r"(bytes), "r"(mbar) : "memory");
}

__device__ __forceinline__ void ldsm4(unsigned& r0, unsigned& r1,
                                      unsigned& r2, unsigned& r3, uint32_t a) {
    asm volatile("ldmatrix.sync.aligned.m8n8.x4.shared.b16 {%0,%1,%2,%3}, [%4];"
                 : "=r"(r0), "=r"(r1), "=r"(r2), "=r"(r3) : "r"(a));
}

__device__ __forceinline__ void mma_bf16(float* d, const unsigned* a,
                                         unsigned b0, unsigned b1) {
    asm volatile(
        "mma.sync.aligned.m16n8k16.row.col.f32.bf16.bf16.f32 "
        "{%0,%1,%2,%3}, {%4,%5,%6,%7}, {%8,%9}, {%0,%1,%2,%3};"
        : "+f"(d[0]), "+f"(d[1]), "+f"(d[2]), "+f"(d[3])
        : "r"(a[0]), "r"(a[1]), "r"(a[2]), "r"(a[3]), "r"(b0), "r"(b1));
}

// ============================================================================
// Kernel 0: wg -> bf16 hi/lo
// ============================================================================
__global__ void __launch_bounds__(256)
wgprep_kernel(const float* __restrict__ wg)
{
    int i = blockIdx.x * 256 + threadIdx.x;     // handles 2 elements
    float a = wg[2 * i], b = wg[2 * i + 1];
    unsigned h = cvt_bf16x2(b, a);
    unsigned l = cvt_bf16x2(b - f_hi(h), a - f_lo(h));
    *(unsigned*)(g_wgh + 2 * i) = h;
    *(unsigned*)(g_wgl + 2 * i) = l;
}

// ============================================================================
// Kernel 1: q/k projection -> bf16 hi/lo (k into padded g_kv tiles)
// ============================================================================
__global__ void __launch_bounds__(256)
proj_qk_kernel(const float* __restrict__ x,
               const float* __restrict__ wq, const float* __restrict__ bq,
               const float* __restrict__ wk, const float* __restrict__ bk)
{
    __shared__ __align__(16) float xs[CH * 32];
    const int b   = blockIdx.y;
    const int n0  = blockIdx.x * 32;
    const int tid = threadIdx.x;

    const float* xb = x + (size_t)b * CH * NN + n0;
    for (int idx = tid; idx < CH * 32; idx += 256) {
        int c = idx >> 5, nn = idx & 31;
        xs[c * 32 + nn] = xb[(size_t)c * NN + nn];
    }
    __syncthreads();

    const int ng = tid & 7;
    const int cg = tid >> 3;
    const bool isq = (cg < 16);
    const float* w    = isq ? wq : wk;
    const float* bias = isq ? bq : bk;
    const int d0 = (isq ? cg : cg - 16) * 2;

    float a0[4], a1[4];
    const float b0 = bias[d0], b1 = bias[d0 + 1];
#pragma unroll
    for (int i = 0; i < 4; i++) { a0[i] = b0; a1[i] = b1; }

    const float* w0p = w + (size_t)d0 * CH;
    const float* w1p = w + (size_t)(d0 + 1) * CH;

    for (int c4 = 0; c4 < CH; c4 += 4) {
        float wr0[4], wr1[4];
        *(float4*)wr0 = *(const float4*)(w0p + c4);
        *(float4*)wr1 = *(const float4*)(w1p + c4);
#pragma unroll
        for (int i = 0; i < 4; i++) {
            float xv[4];
            *(float4*)xv = *(const float4*)(xs + (c4 + i) * 32 + ng * 4);
#pragma unroll
            for (int nn = 0; nn < 4; nn++) {
                a0[nn] += wr0[i] * xv[nn];
                a1[nn] += wr1[i] * xv[nn];
            }
        }
    }

    if (isq) {
#pragma unroll
        for (int nn = 0; nn < 4; nn++) {
            size_t base = ((size_t)b * NN + n0 + ng * 4 + nn) * CQK + d0;
            unsigned h = cvt_bf16x2(a1[nn], a0[nn]);
            unsigned l = cvt_bf16x2(a1[nn] - f_hi(h), a0[nn] - f_lo(h));
            *(unsigned*)(g_qh + base) = h;
            *(unsigned*)(g_ql + base) = l;
        }
    } else {
        const int tile = n0 >> 6;
        const size_t kvb = ((size_t)b * NTILES + tile) * KV_TILE_EL;
#pragma unroll
        for (int nn = 0; nn < 4; nn++) {
            int row = (n0 & 63) + ng * 4 + nn;
            size_t off = kvb + (size_t)row * KPAD + d0;
            unsigned h = cvt_bf16x2(a1[nn], a0[nn]);
            unsigned l = cvt_bf16x2(a1[nn] - f_hi(h), a0[nn] - f_lo(h));
            *(unsigned*)(g_kv + off)        = h;
            *(unsigned*)(g_kv + off + 2560) = l;
        }
    }
}

// ============================================================================
// Kernel 2: v projection -> V region of g_kv (swizzled)
// ============================================================================
__global__ void __launch_bounds__(256)
proj_v_kernel(const float* __restrict__ x,
              const float* __restrict__ wv, const float* __restrict__ bv)
{
    __shared__ __align__(16) float xs[CH * 32];
    const int b   = blockIdx.y;
    const int n0  = blockIdx.x * 32;
    const int tid = threadIdx.x;

    const float* xb = x + (size_t)b * CH * NN + n0;
    for (int idx = tid; idx < CH * 32; idx += 256) {
        int c = idx >> 5, nn = idx & 31;
        xs[c * 32 + nn] = xb[(size_t)c * NN + nn];
    }
    __syncthreads();

    const int ng = tid & 7;
    const int cg = tid >> 3;

    float acc[8][4];
#pragma unroll
    for (int cc = 0; cc < 8; cc++) {
        float bb = bv[cg * 8 + cc];
#pragma unroll
        for (int i = 0; i < 4; i++) acc[cc][i] = bb;
    }

    for (int c4 = 0; c4 < CH; c4 += 4) {
        float xv[4][4];
#pragma unroll
        for (int i = 0; i < 4; i++)
            *(float4*)xv[i] = *(const float4*)(xs + (c4 + i) * 32 + ng * 4);
#pragma unroll
        for (int cc = 0; cc < 8; cc++) {
            float wr[4];
            *(float4*)wr = *(const float4*)(wv + (size_t)(cg * 8 + cc) * CH + c4);
#pragma unroll
            for (int i = 0; i < 4; i++) {
                acc[cc][0] += wr[i] * xv[i][0];
                acc[cc][1] += wr[i] * xv[i][1];
                acc[cc][2] += wr[i] * xv[i][2];
                acc[cc][3] += wr[i] * xv[i][3];
            }
        }
    }

    const int tile = n0 >> 6;
    const int jt   = (n0 & 63) + ng * 4;
    const size_t vb = ((size_t)b * NTILES + tile) * KV_TILE_EL + 5120;
#pragma unroll
    for (int cc = 0; cc < 8; cc++) {
        int c = cg * 8 + cc;
        int off = c * 64 + (((jt >> 3) ^ (c & 7)) << 3) + (jt & 7);
        unsigned h0 = cvt_bf16x2(acc[cc][1], acc[cc][0]);
        unsigned h1 = cvt_bf16x2(acc[cc][3], acc[cc][2]);
        unsigned l0 = cvt_bf16x2(acc[cc][1] - f_hi(h0), acc[cc][0] - f_lo(h0));
        unsigned l1 = cvt_bf16x2(acc[cc][3] - f_hi(h1), acc[cc][2] - f_lo(h1));
        *(uint2*)(g_kv + vb + off)         = make_uint2(h0, h1);
        *(uint2*)(g_kv + vb + 16384 + off) = make_uint2(l0, l1);
    }
}

// ============================================================================
// Kernel 3: HMMA flash attention; ONE cp.async.bulk per tile (K+V together).
// ============================================================================
__global__ void __launch_bounds__(256, 1)
attn_kernel()
{
    extern __shared__ __align__(1024) char smem[];

    const int tid  = threadIdx.x;
    const int w    = tid >> 5;
    const int lane = tid & 31;
    const int g    = lane >> 2;
    const int t    = lane & 3;
    const int b    = blockIdx.y;
    const int q0   = blockIdx.x * TQ;
    const int row0 = q0 + w * 16 + g;

    const uint32_t sb  = smem_u32(smem);
    const uint32_t mb0 = sb + SM_MB0;
    const uint32_t mb1 = sb + SM_MB1;

    if (tid == 0) { MBAR_INIT(mb0, 1); MBAR_INIT(mb1, 1); }
    __syncthreads();

    const __nv_bfloat16* kv_src = g_kv + (size_t)b * NTILES * KV_TILE_EL;

    // ldmatrix per-lane offsets
    const uint32_t k_lm = (uint32_t)(((lane & 7) * KPAD + (lane >> 3) * 8) * 2);
    const int vm = lane >> 3;
    const int vr = lane & 7;
    const uint32_t v_row = (uint32_t)(((vm >> 1) * 8 + vr) * 128);

    // ---- Q A-fragments (persist) ----
    unsigned qh[2][4], ql[2][4];
    {
        const __nv_bfloat16* qhp = g_qh + (size_t)b * NN * CQK;
        const __nv_bfloat16* qlp = g_ql + (size_t)b * NN * CQK;
#pragma unroll
        for (int kq = 0; kq < 2; kq++) {
            int c0 = kq * 16 + t * 2;
            qh[kq][0] = *(const unsigned*)(qhp + (size_t)row0 * CQK + c0);
            qh[kq][1] = *(const unsigned*)(qhp + (size_t)(row0 + 8) * CQK + c0);
            qh[kq][2] = *(const unsigned*)(qhp + (size_t)row0 * CQK + c0 + 8);
            qh[kq][3] = *(const unsigned*)(qhp + (size_t)(row0 + 8) * CQK + c0 + 8);
            ql[kq][0] = *(const unsigned*)(qlp + (size_t)row0 * CQK + c0);
            ql[kq][1] = *(const unsigned*)(qlp + (size_t)(row0 + 8) * CQK + c0);
            ql[kq][2] = *(const unsigned*)(qlp + (size_t)row0 * CQK + c0 + 8);
            ql[kq][3] = *(const unsigned*)(qlp + (size_t)(row0 + 8) * CQK + c0 + 8);
        }
    }

    float o[32][4];
#pragma unroll
    for (int cb = 0; cb < 32; cb++) {
        o[cb][0] = 0.f; o[cb][1] = 0.f; o[cb][2] = 0.f; o[cb][3] = 0.f;
    }
    float rs0 = 0.f, rs1 = 0.f;

    // ---- stage tile 0 ----
    if (tid == 0) {
        MBAR_EXPECT_TX(mb0, KV_TILE_B);
        bulk_g2s(sb + SM_BUF, kv_src, KV_TILE_B, mb0);
    }

    for (int tl = 0; tl < NTILES; tl++) {
        if (tl + 1 < NTILES && tid == 0) {
            uint32_t mb = ((tl + 1) & 1) ? mb1 : mb0;
            MBAR_EXPECT_TX(mb, KV_TILE_B);
            bulk_g2s(sb + SM_BUF + ((tl + 1) & 1) * KV_TILE_B,
                     kv_src + (size_t)(tl + 1) * KV_TILE_EL, KV_TILE_B, mb);
        }
        mbar_wait((tl & 1) ? mb1 : mb0, (tl >> 1) & 1);
        __syncthreads();

        const uint32_t bb  = sb + SM_BUF + (tl & 1) * KV_TILE_B;
        const uint32_t khb = bb + KH_OFF + k_lm;
        const uint32_t klb = bb + KL_OFF + k_lm;
        const uint32_t vhb = bb + V_OFF + v_row;
        const uint32_t vlb = vhb + 32768;

#pragma unroll
        for (int kb = 0; kb < 4; kb++) {
            const uint32_t vsw = (uint32_t)(((kb * 2 + (vm & 1)) ^ vr) * 16);

            float s0a[4] = {0.f, 0.f, 0.f, 0.f};
            float s0b[4] = {0.f, 0.f, 0.f, 0.f};
            float s1a[4] = {0.f, 0.f, 0.f, 0.f};
            float s1b[4] = {0.f, 0.f, 0.f, 0.f};
#pragma unroll
            for (int jbi = 0; jbi < 2; jbi++) {
                const uint32_t koff = (uint32_t)((kb * 2 + jbi) * 8 * KPAD * 2);
                unsigned kh0, kh1, kh2, kh3, kl0, kl1, kl2, kl3;
                ldsm4(kh0, kh1, kh2, kh3, khb + koff);
                ldsm4(kl0, kl1, kl2, kl3, klb + koff);
                float* sa = jbi ? s1a : s0a;
                float* sc = jbi ? s1b : s0b;
                mma_bf16(sa, qh[0], kh0, kh1);
                mma_bf16(sa, qh[0], kl0, kl1);
                mma_bf16(sa, ql[0], kh0, kh1);
                mma_bf16(sc, qh[1], kh2, kh3);
                mma_bf16(sc, qh[1], kl2, kl3);
                mma_bf16(sc, ql[1], kh2, kh3);
            }

            float e00 = __expf(s0a[0] + s0b[0]), e01 = __expf(s0a[1] + s0b[1]);
            float e02 = __expf(s0a[2] + s0b[2]), e03 = __expf(s0a[3] + s0b[3]);
            float e10 = __expf(s1a[0] + s1b[0]), e11 = __expf(s1a[1] + s1b[1]);
            float e12 = __expf(s1a[2] + s1b[2]), e13 = __expf(s1a[3] + s1b[3]);
            rs0 += e00 + e01 + e10 + e11;
            rs1 += e02 + e03 + e12 + e13;

            unsigned pa[4], pl[4];
            pa[0] = cvt_bf16x2(e01, e00);
            pa[1] = cvt_bf16x2(e03, e02);
            pa[2] = cvt_bf16x2(e11, e10);
            pa[3] = cvt_bf16x2(e13, e12);
            pl[0] = cvt_bf16x2(e01 - f_hi(pa[0]), e00 - f_lo(pa[0]));
            pl[1] = cvt_bf16x2(e03 - f_hi(pa[1]), e02 - f_lo(pa[1]));
            pl[2] = cvt_bf16x2(e11 - f_hi(pa[2]), e10 - f_lo(pa[2]));
            pl[3] = cvt_bf16x2(e13 - f_hi(pa[3]), e12 - f_lo(pa[3]));

            uint32_t avh = vhb + vsw;
            uint32_t avl = vlb + vsw;
#pragma unroll
            for (int p = 0; p < 16; p++) {
                unsigned vh0a, vh1a, vh0b, vh1b;
                unsigned vl0a, vl1a, vl0b, vl1b;
                ldsm4(vh0a, vh1a, vh0b, vh1b, avh);
                ldsm4(vl0a, vl1a, vl0b, vl1b, avl);
                mma_bf16(o[2 * p],     pa, vh0a, vh1a);
                mma_bf16(o[2 * p],     pa, vl0a, vl1a);
                mma_bf16(o[2 * p],     pl, vh0a, vh1a);
                mma_bf16(o[2 * p + 1], pa, vh0b, vh1b);
                mma_bf16(o[2 * p + 1], pa, vl0b, vl1b);
                mma_bf16(o[2 * p + 1], pl, vh0b, vh1b);
                avh += 16 * 128;
                avl += 16 * 128;
            }
        }
        __syncthreads();
    }

    rs0 += __shfl_xor_sync(0xffffffffu, rs0, 1);
    rs0 += __shfl_xor_sync(0xffffffffu, rs0, 2);
    rs1 += __shfl_xor_sync(0xffffffffu, rs1, 1);
    rs1 += __shfl_xor_sync(0xffffffffu, rs1, 2);
    const float inv0 = 1.0f / rs0;
    const float inv1 = 1.0f / rs1;

    // ---- write ao as bf16 hi/lo, ldmatrix-swizzled [b][n][c] ----
    const size_t r0b = ((size_t)b * NN + row0) * CH;
    const size_t r1b = ((size_t)b * NN + row0 + 8) * CH;
#pragma unroll
    for (int cb = 0; cb < 32; cb++) {
        size_t off = (size_t)(((cb ^ g) << 3) + t * 2);
        float v0 = o[cb][0] * inv0, v1 = o[cb][1] * inv0;
        unsigned h = cvt_bf16x2(v1, v0);
        unsigned l = cvt_bf16x2(v1 - f_hi(h), v0 - f_lo(h));
        *(unsigned*)(g_aoh + r0b + off) = h;
        *(unsigned*)(g_aol + r0b + off) = l;
        float u0 = o[cb][2] * inv1, u1 = o[cb][3] * inv1;
        unsigned h2 = cvt_bf16x2(u1, u0);
        unsigned l2 = cvt_bf16x2(u1 - f_hi(h2), u0 - f_lo(h2));
        *(unsigned*)(g_aoh + r1b + off) = h2;
        *(unsigned*)(g_aol + r1b + off) = l2;
    }
}

// ============================================================================
// Kernel 4: HMMA output projection + residual.
// CTA: 256 c x 128 n, K = 256. A = wg (gmem frags), B = ao (smem ldmatrix).
// ============================================================================
__global__ void __launch_bounds__(256, 1)
final_kernel(const float* __restrict__ x,
             const float* __restrict__ bg,
             float* __restrict__ y)
{
    extern __shared__ __align__(1024) char smem[];
    const uint32_t sb  = smem_u32(smem);
    const uint32_t mb0 = sb;

    const int tid  = threadIdx.x;
    const int w    = tid >> 5;
    const int lane = tid & 31;
    const int g    = lane >> 2;
    const int t    = lane & 3;
    const int b    = blockIdx.y;
    const int n0   = blockIdx.x * 128;
    const int c0   = w * 32;

    if (tid == 0) MBAR_INIT(mb0, 1);
    __syncthreads();
    if (tid == 0) {
        MBAR_EXPECT_TX(mb0, 131072);
        bulk_g2s(sb + 1024,         g_aoh + ((size_t)b * NN + n0) * CH, 65536, mb0);
        bulk_g2s(sb + 1024 + 65536, g_aol + ((size_t)b * NN + n0) * CH, 65536, mb0);
    }

    float d[2][16][4];
#pragma unroll
    for (int mb = 0; mb < 2; mb++)
#pragma unroll
        for (int nb = 0; nb < 16; nb++) {
            d[mb][nb][0] = 0.f; d[mb][nb][1] = 0.f;
            d[mb][nb][2] = 0.f; d[mb][nb][3] = 0.f;
        }

    const uint32_t ao_row = sb + 1024
        + (uint32_t)(((lane >> 4) * 8 + (lane & 7)) * 512);
    const int chsel = (lane >> 3) & 1;
    const int r7 = lane & 7;

    mbar_wait(mb0, 0);
    __syncthreads();

#pragma unroll 4
    for (int ks = 0; ks < 16; ks++) {
        // A frags (wg) from gmem (L1-resident)
        unsigned ah[2][4], al[2][4];
#pragma unroll
        for (int mb = 0; mb < 2; mb++) {
            int cr  = c0 + mb * 16 + g;
            int col = ks * 16 + t * 2;
            ah[mb][0] = *(const unsigned*)(g_wgh + cr * CH + col);
            ah[mb][1] = *(const unsigned*)(g_wgh + (cr + 8) * CH + col);
            ah[mb][2] = *(const unsigned*)(g_wgh + cr * CH + col + 8);
            ah[mb][3] = *(const unsigned*)(g_wgh + (cr + 8) * CH + col + 8);
            al[mb][0] = *(const unsigned*)(g_wgl + cr * CH + col);
            al[mb][1] = *(const unsigned*)(g_wgl + (cr + 8) * CH + col);
            al[mb][2] = *(const unsigned*)(g_wgl + cr * CH + col + 8);
            al[mb][3] = *(const unsigned*)(g_wgl + (cr + 8) * CH + col + 8);
        }

        const uint32_t sw = (uint32_t)((((2 * ks + chsel) ^ r7)) * 16);
#pragma unroll
        for (int p = 0; p < 8; p++) {
            uint32_t addr = ao_row + (uint32_t)(p * 16 * 512) + sw;
            unsigned bh0, bh1, bh2, bh3, bl0, bl1, bl2, bl3;
            ldsm4(bh0, bh1, bh2, bh3, addr);
            ldsm4(bl0, bl1, bl2, bl3, addr + 65536);
#pragma unroll
            for (int mb = 0; mb < 2; mb++) {
                mma_bf16(d[mb][2 * p],     ah[mb], bh0, bh1);
                mma_bf16(d[mb][2 * p],     ah[mb], bl0, bl1);
                mma_bf16(d[mb][2 * p],     al[mb], bh0, bh1);
                mma_bf16(d[mb][2 * p + 1], ah[mb], bh2, bh3);
                mma_bf16(d[mb][2 * p + 1], ah[mb], bl2, bl3);
                mma_bf16(d[mb][2 * p + 1], al[mb], bh2, bh3);
            }
        }
    }

    // epilogue: y = x + bg + D
#pragma unroll
    for (int mb = 0; mb < 2; mb++) {
        int cA = c0 + mb * 16 + g;
        int cB = cA + 8;
        float bgA = bg[cA], bgB = bg[cB];
        const float* xA = x + ((size_t)b * CH + cA) * NN + n0 + t * 2;
        const float* xB = x + ((size_t)b * CH + cB) * NN + n0 + t * 2;
        float* yA = y + ((size_t)b * CH + cA) * NN + n0 + t * 2;
        float* yB = y + ((size_t)b * CH + cB) * NN + n0 + t * 2;
#pragma unroll
        for (int nb = 0; nb < 16; nb++) {
            float2 xr = *(const float2*)(xA + nb * 8);
            *(float2*)(yA + nb * 8) =
                make_float2(xr.x + bgA + d[mb][nb][0],
                            xr.y + bgA + d[mb][nb][1]);
            float2 xs2 = *(const float2*)(xB + nb * 8);
            *(float2*)(yB + nb * 8) =
                make_float2(xs2.x + bgB + d[mb][nb][2],
                            xs2.y + bgB + d[mb][nb][3]);
        }
    }
}

// ============================================================================
extern "C" void kernel_launch(void* const* d_in, const int* in_sizes, int n_in,
                              void* d_out, int out_size)
{
    const float* x  = (const float*)d_in[0];
    const float* wq = (const float*)d_in[1];
    const float* bq = (const float*)d_in[2];
    const float* wk = (const float*)d_in[3];
    const float* bk = (const float*)d_in[4];
    const float* wv = (const float*)d_in[5];
    const float* bv = (const float*)d_in[6];
    const float* wg = (const float*)d_in[7];
    const float* bg = (const float*)d_in[8];
    float* y = (float*)d_out;

    cudaFuncSetAttribute(attn_kernel,
                         cudaFuncAttributeMaxDynamicSharedMemorySize, SM_TOTAL);
    cudaFuncSetAttribute(final_kernel,
                         cudaFuncAttributeMaxDynamicSharedMemorySize, FIN_SM_TOTAL);

    wgprep_kernel <<<CH * CH / 512, 256>>>(wg);
    proj_qk_kernel<<<dim3(NN / 32, BATCH), 256>>>(x, wq, bq, wk, bk);
    proj_v_kernel <<<dim3(NN / 32, BATCH), 256>>>(x, wv, bv);
    attn_kernel   <<<dim3(NN / TQ, BATCH), 256, SM_TOTAL>>>();
    final_kernel  <<<dim3(NN / 128, BATCH), 256, FIN_SM_TOTAL>>>(x, bg, y);
}

// round 10
// speedup vs baseline: 1.7670x; 1.1430x over previous
#include <cuda_runtime.h>
#include <cuda_bf16.h>
#include <cstdint>

#define BATCH 4
#define CH    256
#define CQK   32
#define NN    4096

#define TQ     128
#define TJ     64
#define NTILES (NN / TJ)   // 64

// ---- unified KV tile (bf16 elements): [KH 64x40][KL 64x40][VH 256x64][VL 256x64]
#define KPAD       40
#define KV_TILE_EL 37888
#define KV_TILE_B  75776
#define KH_OFF     0
#define KL_OFF     5120
#define V_OFF      10240
#define SM_MB0  0
#define SM_MB1  8
#define SM_BUF  1024
#define SM_TOTAL (SM_BUF + 2 * KV_TILE_B)   // 152576

// GEMM kernels SMEM: [mbar pad 1024][B_hi 64KB][B_lo 64KB]
#define GEMM_SM_TOTAL (1024 + 2 * 65536)

// ---------------- scratch (device globals; no allocation allowed) ----------
__device__ __nv_bfloat16 g_qh[(size_t)BATCH * NN * CQK];
__device__ __nv_bfloat16 g_ql[(size_t)BATCH * NN * CQK];
__device__ __align__(128) __nv_bfloat16 g_kv[(size_t)BATCH * NTILES * KV_TILE_EL];
__device__ __align__(128) __nv_bfloat16 g_aoh[(size_t)BATCH * NN * CH];  // swizzled
__device__ __align__(128) __nv_bfloat16 g_aol[(size_t)BATCH * NN * CH];
__device__ __align__(128) __nv_bfloat16 g_xh[(size_t)BATCH * NN * CH];   // x^T swizzled
__device__ __align__(128) __nv_bfloat16 g_xl[(size_t)BATCH * NN * CH];
__device__ __nv_bfloat16 g_wgh[CH * CH];
__device__ __nv_bfloat16 g_wgl[CH * CH];
__device__ __nv_bfloat16 g_wh[320 * CH];   // [wv;wq;wk] hi
__device__ __nv_bfloat16 g_wl[320 * CH];
__device__ float         g_bqkv[320];

// ---------------- helpers ---------------------------------------------------
__device__ __forceinline__ unsigned cvt_bf16x2(float hi, float lo) {
    unsigned r;
    asm("cvt.rn.bf16x2.f32 %0, %1, %2;" : "=r"(r) : "f"(hi), "f"(lo));
    return r;
}
__device__ __forceinline__ float f_lo(unsigned u) { return __uint_as_float(u << 16); }
__device__ __forceinline__ float f_hi(unsigned u) { return __uint_as_float(u & 0xffff0000u); }

__device__ __forceinline__ uint32_t smem_u32(const void* p) {
    uint32_t a;
    asm("{ .reg .u64 t; cvta.to.shared.u64 t, %1; cvt.u32.u64 %0, t; }"
        : "=r"(a) : "l"(p));
    return a;
}

#define MBAR_INIT(addr, cnt) \
    asm volatile("mbarrier.init.shared.b64 [%0], %1;" :: "r"(addr), "r"(cnt) : "memory")
#define MBAR_EXPECT_TX(addr, bytes) \
    asm volatile("mbarrier.arrive.expect_tx.shared.b64 _, [%0], %1;" \
                 :: "r"(addr), "r"(bytes) : "memory")

__device__ __forceinline__ void mbar_wait(uint32_t addr, uint32_t parity) {
    asm volatile(
        "{\n\t.reg .pred P;\n\t"
        "WL_%=:\n\t"
        "mbarrier.try_wait.parity.acquire.cta.shared::cta.b64 P, [%0], %1, 0x989680;\n\t"
        "@P bra WD_%=;\n\t"
        "bra WL_%=;\n\t"
        "WD_%=:\n\t}"
        :: "r"(addr), "r"(parity) : "memory");
}
__device__ __forceinline__ void bulk_g2s(uint32_t dst, const void* src,
                                         uint32_t bytes, uint32_t mbar) {
    asm volatile(
        "cp.async.bulk.shared::cluster.global.mbarrier::complete_tx::bytes "
        "[%0], [%1], %2, [%3];"
        :: "r"(dst), "l"(src), "r"(bytes), "r"(mbar) : "memory");
}

__device__ __forceinline__ void ldsm4(unsigned& r0, unsigned& r1,
                                      unsigned& r2, unsigned& r3, uint32_t a) {
    asm volatile("ldmatrix.sync.aligned.m8n8.x4.shared.b16 {%0,%1,%2,%3}, [%4];"
                 : "=r"(r0), "=r"(r1), "=r"(r2), "=r"(r3) : "r"(a));
}

__device__ __forceinline__ void mma_bf16(float* d, const unsigned* a,
                                         unsigned b0, unsigned b1) {
    asm volatile(
        "mma.sync.aligned.m16n8k16.row.col.f32.bf16.bf16.f32 "
        "{%0,%1,%2,%3}, {%4,%5,%6,%7}, {%8,%9}, {%0,%1,%2,%3};"
        : "+f"(d[0]), "+f"(d[1]), "+f"(d[2]), "+f"(d[3])
        : "r"(a[0]), "r"(a[1]), "r"(a[2]), "r"(a[3]), "r"(b0), "r"(b1));
}

// ============================================================================
// Kernel P0: wg -> bf16 hi/lo
// ============================================================================
__global__ void __launch_bounds__(256)
wgprep_kernel(const float* __restrict__ wg)
{
    int i = blockIdx.x * 256 + threadIdx.x;
    float a = wg[2 * i], b = wg[2 * i + 1];
    unsigned h = cvt_bf16x2(b, a);
    unsigned l = cvt_bf16x2(b - f_hi(h), a - f_lo(h));
    *(unsigned*)(g_wgh + 2 * i) = h;
    *(unsigned*)(g_wgl + 2 * i) = l;
}

// ============================================================================
// Kernel P1: stacked [wv;wq;wk] -> bf16 hi/lo + combined bias
// ============================================================================
__global__ void __launch_bounds__(256)
wqkvprep_kernel(const float* __restrict__ wv, const float* __restrict__ bv,
                const float* __restrict__ wq, const float* __restrict__ bq,
                const float* __restrict__ wk, const float* __restrict__ bk)
{
    int i = blockIdx.x * 256 + threadIdx.x;   // 0..40959, 2 els each
    int row  = i >> 7;
    int col2 = (i & 127) * 2;
    const float* src = (row < 256) ? wv + row * CH
                     : (row < 288) ? wq + (row - 256) * CH
                                   : wk + (row - 288) * CH;
    float a = src[col2], b = src[col2 + 1];
    unsigned h = cvt_bf16x2(b, a);
    unsigned l = cvt_bf16x2(b - f_hi(h), a - f_lo(h));
    *(unsigned*)(g_wh + row * CH + col2) = h;
    *(unsigned*)(g_wl + row * CH + col2) = l;
    if (i < 320)
        g_bqkv[i] = (i < 256) ? bv[i] : (i < 288) ? bq[i - 256] : bk[i - 288];
}

// ============================================================================
// Kernel P2: x [b][c][n] fp32 -> x^T [b][n][c] bf16 hi/lo, ldmatrix-swizzled
// (row n: data chunk ch (8 els,16B) stored at memory chunk ch ^ (n&7))
// ============================================================================
__global__ void __launch_bounds__(256)
xprep_kernel(const float* __restrict__ x)
{
    __shared__ __align__(16) float xs[CH * 33];
    const int b   = blockIdx.y;
    const int n0  = blockIdx.x * 32;
    const int tid = threadIdx.x;

    const float* xb = x + (size_t)b * CH * NN + n0;
    for (int idx = tid; idx < CH * 32; idx += 256) {
        int c = idx >> 5, n = idx & 31;
        xs[c * 33 + n] = xb[(size_t)c * NN + n];
    }
    __syncthreads();

    const int n   = tid & 31;
    const int g3  = tid >> 5;          // 4 chunks each
    const int nsw = (n0 + n) & 7;
    __nv_bfloat16* dh = g_xh + ((size_t)b * NN + n0 + n) * CH;
    __nv_bfloat16* dl = g_xl + ((size_t)b * NN + n0 + n) * CH;

#pragma unroll
    for (int cc = 0; cc < 4; cc++) {
        int ch = g3 * 4 + cc;
        float v[8];
#pragma unroll
        for (int j = 0; j < 8; j++) v[j] = xs[(ch * 8 + j) * 33 + n];
        unsigned h[4], l[4];
#pragma unroll
        for (int j = 0; j < 4; j++) {
            h[j] = cvt_bf16x2(v[2 * j + 1], v[2 * j]);
            l[j] = cvt_bf16x2(v[2 * j + 1] - f_hi(h[j]), v[2 * j] - f_lo(h[j]));
        }
        int mch = (ch ^ nsw) << 3;
        *(uint4*)(dh + mch) = make_uint4(h[0], h[1], h[2], h[3]);
        *(uint4*)(dl + mch) = make_uint4(l[0], l[1], l[2], l[3]);
    }
}

// ============================================================================
// Kernel P3: fused q/k/v projection via HMMA.
// CTA: 320 rows x 128 n, K=256. 10 warps. Epilogue scatters q, K, V.
// ============================================================================
__global__ void __launch_bounds__(320, 1)
qkv_kernel()
{
    extern __shared__ __align__(1024) char smem[];
    const uint32_t sb  = smem_u32(smem);
    const uint32_t mb0 = sb;

    const int tid  = threadIdx.x;
    const int w    = tid >> 5;
    const int lane = tid & 31;
    const int g    = lane >> 2;
    const int t    = lane & 3;
    const int b    = blockIdx.y;
    const int n0   = blockIdx.x * 128;
    const int c0   = w * 32;

    if (tid == 0) MBAR_INIT(mb0, 1);
    __syncthreads();
    if (tid == 0) {
        MBAR_EXPECT_TX(mb0, 131072);
        bulk_g2s(sb + 1024,         g_xh + ((size_t)b * NN + n0) * CH, 65536, mb0);
        bulk_g2s(sb + 1024 + 65536, g_xl + ((size_t)b * NN + n0) * CH, 65536, mb0);
    }

    float d[2][16][4];
#pragma unroll
    for (int mb = 0; mb < 2; mb++)
#pragma unroll
        for (int nb = 0; nb < 16; nb++) {
            d[mb][nb][0] = 0.f; d[mb][nb][1] = 0.f;
            d[mb][nb][2] = 0.f; d[mb][nb][3] = 0.f;
        }

    const uint32_t b_row = sb + 1024
        + (uint32_t)(((lane >> 4) * 8 + (lane & 7)) * 512);
    const int chsel = (lane >> 3) & 1;
    const int r7 = lane & 7;

    mbar_wait(mb0, 0);
    __syncthreads();

#pragma unroll 4
    for (int ks = 0; ks < 16; ks++) {
        unsigned ah[2][4], al[2][4];
#pragma unroll
        for (int mb = 0; mb < 2; mb++) {
            int cr  = c0 + mb * 16 + g;
            int col = ks * 16 + t * 2;
            ah[mb][0] = *(const unsigned*)(g_wh + cr * CH + col);
            ah[mb][1] = *(const unsigned*)(g_wh + (cr + 8) * CH + col);
            ah[mb][2] = *(const unsigned*)(g_wh + cr * CH + col + 8);
            ah[mb][3] = *(const unsigned*)(g_wh + (cr + 8) * CH + col + 8);
            al[mb][0] = *(const unsigned*)(g_wl + cr * CH + col);
            al[mb][1] = *(const unsigned*)(g_wl + (cr + 8) * CH + col);
            al[mb][2] = *(const unsigned*)(g_wl + cr * CH + col + 8);
            al[mb][3] = *(const unsigned*)(g_wl + (cr + 8) * CH + col + 8);
        }

        const uint32_t sw = (uint32_t)(((2 * ks + chsel) ^ r7) * 16);
#pragma unroll
        for (int p = 0; p < 8; p++) {
            uint32_t addr = b_row + (uint32_t)(p * 16 * 512) + sw;
            unsigned bh0, bh1, bh2, bh3, bl0, bl1, bl2, bl3;
            ldsm4(bh0, bh1, bh2, bh3, addr);
            ldsm4(bl0, bl1, bl2, bl3, addr + 65536);
#pragma unroll
            for (int mb = 0; mb < 2; mb++) {
                mma_bf16(d[mb][2 * p],     ah[mb], bh0, bh1);
                mma_bf16(d[mb][2 * p],     ah[mb], bl0, bl1);
                mma_bf16(d[mb][2 * p],     al[mb], bh0, bh1);
                mma_bf16(d[mb][2 * p + 1], ah[mb], bh2, bh3);
                mma_bf16(d[mb][2 * p + 1], ah[mb], bl2, bl3);
                mma_bf16(d[mb][2 * p + 1], al[mb], bh2, bh3);
            }
        }
    }

    // ---- epilogue: scatter to V (warps 0-7), q (warp 8), K (warp 9) ----
    const size_t kvbase = (size_t)b * NTILES * KV_TILE_EL;
#pragma unroll
    for (int mb = 0; mb < 2; mb++) {
        int rA = c0 + mb * 16 + g;
        int rB = rA + 8;
        float biasA = g_bqkv[rA], biasB = g_bqkv[rB];
#pragma unroll
        for (int nb = 0; nb < 16; nb++) {
            int n    = n0 + nb * 8 + t * 2;
            int tile = n >> 6;
            int jt   = n & 63;
            size_t kvb = kvbase + (size_t)tile * KV_TILE_EL;
            float vA0 = d[mb][nb][0] + biasA, vA1 = d[mb][nb][1] + biasA;
            float vB0 = d[mb][nb][2] + biasB, vB1 = d[mb][nb][3] + biasB;
            if (w < 8) {
                // V: swizzled [c][j]
                size_t vb = kvb + 5120;
                unsigned hA = cvt_bf16x2(vA1, vA0);
                unsigned lA = cvt_bf16x2(vA1 - f_hi(hA), vA0 - f_lo(hA));
                size_t offA = (size_t)rA * 64 + (((jt >> 3) ^ (rA & 7)) << 3) + (jt & 7);
                *(unsigned*)(g_kv + vb + offA)         = hA;
                *(unsigned*)(g_kv + vb + 16384 + offA) = lA;
                unsigned hB = cvt_bf16x2(vB1, vB0);
                unsigned lB = cvt_bf16x2(vB1 - f_hi(hB), vB0 - f_lo(hB));
                size_t offB = (size_t)rB * 64 + (((jt >> 3) ^ (rB & 7)) << 3) + (jt & 7);
                *(unsigned*)(g_kv + vb + offB)         = hB;
                *(unsigned*)(g_kv + vb + 16384 + offB) = lB;
            } else if (w == 8) {
                // q: [b][n][d]
                int dA = rA - 256, dB = rB - 256;
                size_t r0 = ((size_t)b * NN + n) * CQK;
                size_t r1 = r0 + CQK;
                __nv_bfloat16 hA0 = __float2bfloat16(vA0);
                __nv_bfloat16 hA1 = __float2bfloat16(vA1);
                g_qh[r0 + dA] = hA0; g_ql[r0 + dA] = __float2bfloat16(vA0 - __bfloat162float(hA0));
                g_qh[r1 + dA] = hA1; g_ql[r1 + dA] = __float2bfloat16(vA1 - __bfloat162float(hA1));
                __nv_bfloat16 hB0 = __float2bfloat16(vB0);
                __nv_bfloat16 hB1 = __float2bfloat16(vB1);
                g_qh[r0 + dB] = hB0; g_ql[r0 + dB] = __float2bfloat16(vB0 - __bfloat162float(hB0));
                g_qh[r1 + dB] = hB1; g_ql[r1 + dB] = __float2bfloat16(vB1 - __bfloat162float(hB1));
            } else {
                // K: [j][d] pad 40, hi at 0, lo at +2560 elements
                int dA = rA - 288, dB = rB - 288;
                size_t k0 = kvb + (size_t)jt * KPAD;
                size_t k1 = k0 + KPAD;
                __nv_bfloat16 hA0 = __float2bfloat16(vA0);
                __nv_bfloat16 hA1 = __float2bfloat16(vA1);
                g_kv[k0 + dA] = hA0; g_kv[k0 + 2560 + dA] = __float2bfloat16(vA0 - __bfloat162float(hA0));
                g_kv[k1 + dA] = hA1; g_kv[k1 + 2560 + dA] = __float2bfloat16(vA1 - __bfloat162float(hA1));
                __nv_bfloat16 hB0 = __float2bfloat16(vB0);
                __nv_bfloat16 hB1 = __float2bfloat16(vB1);
                g_kv[k0 + dB] = hB0; g_kv[k0 + 2560 + dB] = __float2bfloat16(vB0 - __bfloat162float(hB0));
                g_kv[k1 + dB] = hB1; g_kv[k1 + 2560 + dB] = __float2bfloat16(vB1 - __bfloat162float(hB1));
            }
        }
    }
}

// ============================================================================
// Kernel 3: HMMA flash attention (unchanged from R9)
// ============================================================================
__global__ void __launch_bounds__(256, 1)
attn_kernel()
{
    extern __shared__ __align__(1024) char smem[];

    const int tid  = threadIdx.x;
    const int w    = tid >> 5;
    const int lane = tid & 31;
    const int g    = lane >> 2;
    const int t    = lane & 3;
    const int b    = blockIdx.y;
    const int q0   = blockIdx.x * TQ;
    const int row0 = q0 + w * 16 + g;

    const uint32_t sb  = smem_u32(smem);
    const uint32_t mb0 = sb + SM_MB0;
    const uint32_t mb1 = sb + SM_MB1;

    if (tid == 0) { MBAR_INIT(mb0, 1); MBAR_INIT(mb1, 1); }
    __syncthreads();

    const __nv_bfloat16* kv_src = g_kv + (size_t)b * NTILES * KV_TILE_EL;

    const uint32_t k_lm = (uint32_t)(((lane & 7) * KPAD + (lane >> 3) * 8) * 2);
    const int vm = lane >> 3;
    const int vr = lane & 7;
    const uint32_t v_row = (uint32_t)(((vm >> 1) * 8 + vr) * 128);

    unsigned qh[2][4], ql[2][4];
    {
        const __nv_bfloat16* qhp = g_qh + (size_t)b * NN * CQK;
        const __nv_bfloat16* qlp = g_ql + (size_t)b * NN * CQK;
#pragma unroll
        for (int kq = 0; kq < 2; kq++) {
            int c0 = kq * 16 + t * 2;
            qh[kq][0] = *(const unsigned*)(qhp + (size_t)row0 * CQK + c0);
            qh[kq][1] = *(const unsigned*)(qhp + (size_t)(row0 + 8) * CQK + c0);
            qh[kq][2] = *(const unsigned*)(qhp + (size_t)row0 * CQK + c0 + 8);
            qh[kq][3] = *(const unsigned*)(qhp + (size_t)(row0 + 8) * CQK + c0 + 8);
            ql[kq][0] = *(const unsigned*)(qlp + (size_t)row0 * CQK + c0);
            ql[kq][1] = *(const unsigned*)(qlp + (size_t)(row0 + 8) * CQK + c0);
            ql[kq][2] = *(const unsigned*)(qlp + (size_t)row0 * CQK + c0 + 8);
            ql[kq][3] = *(const unsigned*)(qlp + (size_t)(row0 + 8) * CQK + c0 + 8);
        }
    }

    float o[32][4];
#pragma unroll
    for (int cb = 0; cb < 32; cb++) {
        o[cb][0] = 0.f; o[cb][1] = 0.f; o[cb][2] = 0.f; o[cb][3] = 0.f;
    }
    float rs0 = 0.f, rs1 = 0.f;

    if (tid == 0) {
        MBAR_EXPECT_TX(mb0, KV_TILE_B);
        bulk_g2s(sb + SM_BUF, kv_src, KV_TILE_B, mb0);
    }

    for (int tl = 0; tl < NTILES; tl++) {
        if (tl + 1 < NTILES && tid == 0) {
            uint32_t mb = ((tl + 1) & 1) ? mb1 : mb0;
            MBAR_EXPECT_TX(mb, KV_TILE_B);
            bulk_g2s(sb + SM_BUF + ((tl + 1) & 1) * KV_TILE_B,
                     kv_src + (size_t)(tl + 1) * KV_TILE_EL, KV_TILE_B, mb);
        }
        mbar_wait((tl & 1) ? mb1 : mb0, (tl >> 1) & 1);
        __syncthreads();

        const uint32_t bb  = sb + SM_BUF + (tl & 1) * KV_TILE_B;
        const uint32_t khb = bb + KH_OFF + k_lm;
        const uint32_t klb = bb + KL_OFF + k_lm;
        const uint32_t vhb = bb + V_OFF + v_row;
        const uint32_t vlb = vhb + 32768;

#pragma unroll
        for (int kb = 0; kb < 4; kb++) {
            const uint32_t vsw = (uint32_t)(((kb * 2 + (vm & 1)) ^ vr) * 16);

            float s0a[4] = {0.f, 0.f, 0.f, 0.f};
            float s0b[4] = {0.f, 0.f, 0.f, 0.f};
            float s1a[4] = {0.f, 0.f, 0.f, 0.f};
            float s1b[4] = {0.f, 0.f, 0.f, 0.f};
#pragma unroll
            for (int jbi = 0; jbi < 2; jbi++) {
                const uint32_t koff = (uint32_t)((kb * 2 + jbi) * 8 * KPAD * 2);
                unsigned kh0, kh1, kh2, kh3, kl0, kl1, kl2, kl3;
                ldsm4(kh0, kh1, kh2, kh3, khb + koff);
                ldsm4(kl0, kl1, kl2, kl3, klb + koff);
                float* sa = jbi ? s1a : s0a;
                float* sc = jbi ? s1b : s0b;
                mma_bf16(sa, qh[0], kh0, kh1);
                mma_bf16(sa, qh[0], kl0, kl1);
                mma_bf16(sa, ql[0], kh0, kh1);
                mma_bf16(sc, qh[1], kh2, kh3);
                mma_bf16(sc, qh[1], kl2, kl3);
                mma_bf16(sc, ql[1], kh2, kh3);
            }

            float e00 = __expf(s0a[0] + s0b[0]), e01 = __expf(s0a[1] + s0b[1]);
            float e02 = __expf(s0a[2] + s0b[2]), e03 = __expf(s0a[3] + s0b[3]);
            float e10 = __expf(s1a[0] + s1b[0]), e11 = __expf(s1a[1] + s1b[1]);
            float e12 = __expf(s1a[2] + s1b[2]), e13 = __expf(s1a[3] + s1b[3]);
            rs0 += e00 + e01 + e10 + e11;
            rs1 += e02 + e03 + e12 + e13;

            unsigned pa[4], pl[4];
            pa[0] = cvt_bf16x2(e01, e00);
            pa[1] = cvt_bf16x2(e03, e02);
            pa[2] = cvt_bf16x2(e11, e10);
            pa[3] = cvt_bf16x2(e13, e12);
            pl[0] = cvt_bf16x2(e01 - f_hi(pa[0]), e00 - f_lo(pa[0]));
            pl[1] = cvt_bf16x2(e03 - f_hi(pa[1]), e02 - f_lo(pa[1]));
            pl[2] = cvt_bf16x2(e11 - f_hi(pa[2]), e10 - f_lo(pa[2]));
            pl[3] = cvt_bf16x2(e13 - f_hi(pa[3]), e12 - f_lo(pa[3]));

            uint32_t avh = vhb + vsw;
            uint32_t avl = vlb + vsw;
#pragma unroll
            for (int p = 0; p < 16; p++) {
                unsigned vh0a, vh1a, vh0b, vh1b;
                unsigned vl0a, vl1a, vl0b, vl1b;
                ldsm4(vh0a, vh1a, vh0b, vh1b, avh);
                ldsm4(vl0a, vl1a, vl0b, vl1b, avl);
                mma_bf16(o[2 * p],     pa, vh0a, vh1a);
                mma_bf16(o[2 * p],     pa, vl0a, vl1a);
                mma_bf16(o[2 * p],     pl, vh0a, vh1a);
                mma_bf16(o[2 * p + 1], pa, vh0b, vh1b);
                mma_bf16(o[2 * p + 1], pa, vl0b, vl1b);
                mma_bf16(o[2 * p + 1], pl, vh0b, vh1b);
                avh += 16 * 128;
                avl += 16 * 128;
            }
        }
        __syncthreads();
    }

    rs0 += __shfl_xor_sync(0xffffffffu, rs0, 1);
    rs0 += __shfl_xor_sync(0xffffffffu, rs0, 2);
    rs1 += __shfl_xor_sync(0xffffffffu, rs1, 1);
    rs1 += __shfl_xor_sync(0xffffffffu, rs1, 2);
    const float inv0 = 1.0f / rs0;
    const float inv1 = 1.0f / rs1;

    const size_t r0b = ((size_t)b * NN + row0) * CH;
    const size_t r1b = ((size_t)b * NN + row0 + 8) * CH;
#pragma unroll
    for (int cb = 0; cb < 32; cb++) {
        size_t off = (size_t)(((cb ^ g) << 3) + t * 2);
        float v0 = o[cb][0] * inv0, v1 = o[cb][1] * inv0;
        unsigned h = cvt_bf16x2(v1, v0);
        unsigned l = cvt_bf16x2(v1 - f_hi(h), v0 - f_lo(h));
        *(unsigned*)(g_aoh + r0b + off) = h;
        *(unsigned*)(g_aol + r0b + off) = l;
        float u0 = o[cb][2] * inv1, u1 = o[cb][3] * inv1;
        unsigned h2 = cvt_bf16x2(u1, u0);
        unsigned l2 = cvt_bf16x2(u1 - f_hi(h2), u0 - f_lo(h2));
        *(unsigned*)(g_aoh + r1b + off) = h2;
        *(unsigned*)(g_aol + r1b + off) = l2;
    }
}

// ============================================================================
// Kernel 4: HMMA output projection + residual (unchanged from R9)
// ============================================================================
__global__ void __launch_bounds__(256, 1)
final_kernel(const float* __restrict__ x,
             const float* __restrict__ bg,
             float* __restrict__ y)
{
    extern __shared__ __align__(1024) char smem[];
    const uint32_t sb  = smem_u32(smem);
    const uint32_t mb0 = sb;

    const int tid  = threadIdx.x;
    const int w    = tid >> 5;
    const int lane = tid & 31;
    const int g    = lane >> 2;
    const int t    = lane & 3;
    const int b    = blockIdx.y;
    const int n0   = blockIdx.x * 128;
    const int c0   = w * 32;

    if (tid == 0) MBAR_INIT(mb0, 1);
    __syncthreads();
    if (tid == 0) {
        MBAR_EXPECT_TX(mb0, 131072);
        bulk_g2s(sb + 1024,         g_aoh + ((size_t)b * NN + n0) * CH, 65536, mb0);
        bulk_g2s(sb + 1024 + 65536, g_aol + ((size_t)b * NN + n0) * CH, 65536, mb0);
    }

    float d[2][16][4];
#pragma unroll
    for (int mb = 0; mb < 2; mb++)
#pragma unroll
        for (int nb = 0; nb < 16; nb++) {
            d[mb][nb][0] = 0.f; d[mb][nb][1] = 0.f;
            d[mb][nb][2] = 0.f; d[mb][nb][3] = 0.f;
        }

    const uint32_t ao_row = sb + 1024
        + (uint32_t)(((lane >> 4) * 8 + (lane & 7)) * 512);
    const int chsel = (lane >> 3) & 1;
    const int r7 = lane & 7;

    mbar_wait(mb0, 0);
    __syncthreads();

#pragma unroll 4
    for (int ks = 0; ks < 16; ks++) {
        unsigned ah[2][4], al[2][4];
#pragma unroll
        for (int mb = 0; mb < 2; mb++) {
            int cr  = c0 + mb * 16 + g;
            int col = ks * 16 + t * 2;
            ah[mb][0] = *(const unsigned*)(g_wgh + cr * CH + col);
            ah[mb][1] = *(const unsigned*)(g_wgh + (cr + 8) * CH + col);
            ah[mb][2] = *(const unsigned*)(g_wgh + cr * CH + col + 8);
            ah[mb][3] = *(const unsigned*)(g_wgh + (cr + 8) * CH + col + 8);
            al[mb][0] = *(const unsigned*)(g_wgl + cr * CH + col);
            al[mb][1] = *(const unsigned*)(g_wgl + (cr + 8) * CH + col);
            al[mb][2] = *(const unsigned*)(g_wgl + cr * CH + col + 8);
            al[mb][3] = *(const unsigned*)(g_wgl + (cr + 8) * CH + col + 8);
        }

        const uint32_t sw = (uint32_t)((((2 * ks + chsel) ^ r7)) * 16);
#pragma unroll
        for (int p = 0; p < 8; p++) {
            uint32_t addr = ao_row + (uint32_t)(p * 16 * 512) + sw;
            unsigned bh0, bh1, bh2, bh3, bl0, bl1, bl2, bl3;
            ldsm4(bh0, bh1, bh2, bh3, addr);
            ldsm4(bl0, bl1, bl2, bl3, addr + 65536);
#pragma unroll
            for (int mb = 0; mb < 2; mb++) {
                mma_bf16(d[mb][2 * p],     ah[mb], bh0, bh1);
                mma_bf16(d[mb][2 * p],     ah[mb], bl0, bl1);
                mma_bf16(d[mb][2 * p],     al[mb], bh0, bh1);
                mma_bf16(d[mb][2 * p + 1], ah[mb], bh2, bh3);
                mma_bf16(d[mb][2 * p + 1], ah[mb], bl2, bl3);
                mma_bf16(d[mb][2 * p + 1], al[mb], bh2, bh3);
            }
        }
    }

#pragma unroll
    for (int mb = 0; mb < 2; mb++) {
        int cA = c0 + mb * 16 + g;
        int cB = cA + 8;
        float bgA = bg[cA], bgB = bg[cB];
        const float* xA = x + ((size_t)b * CH + cA) * NN + n0 + t * 2;
        const float* xB = x + ((size_t)b * CH + cB) * NN + n0 + t * 2;
        float* yA = y + ((size_t)b * CH + cA) * NN + n0 + t * 2;
        float* yB = y + ((size_t)b * CH + cB) * NN + n0 + t * 2;
#pragma unroll
        for (int nb = 0; nb < 16; nb++) {
            float2 xr = *(const float2*)(xA + nb * 8);
            *(float2*)(yA + nb * 8) =
                make_float2(xr.x + bgA + d[mb][nb][0],
                            xr.y + bgA + d[mb][nb][1]);
            float2 xs2 = *(const float2*)(xB + nb * 8);
            *(float2*)(yB + nb * 8) =
                make_float2(xs2.x + bgB + d[mb][nb][2],
                            xs2.y + bgB + d[mb][nb][3]);
        }
    }
}

// ============================================================================
extern "C" void kernel_launch(void* const* d_in, const int* in_sizes, int n_in,
                              void* d_out, int out_size)
{
    const float* x  = (const float*)d_in[0];
    const float* wq = (const float*)d_in[1];
    const float* bq = (const float*)d_in[2];
    const float* wk = (const float*)d_in[3];
    const float* bk = (const float*)d_in[4];
    const float* wv = (const float*)d_in[5];
    const float* bv = (const float*)d_in[6];
    const float* wg = (const float*)d_in[7];
    const float* bg = (const float*)d_in[8];
    float* y = (float*)d_out;

    cudaFuncSetAttribute(attn_kernel,
                         cudaFuncAttributeMaxDynamicSharedMemorySize, SM_TOTAL);
    cudaFuncSetAttribute(qkv_kernel,
                         cudaFuncAttributeMaxDynamicSharedMemorySize, GEMM_SM_TOTAL);
    cudaFuncSetAttribute(final_kernel,
                         cudaFuncAttributeMaxDynamicSharedMemorySize, GEMM_SM_TOTAL);

    wgprep_kernel  <<<CH * CH / 512, 256>>>(wg);
    wqkvprep_kernel<<<320 * CH / 512, 256>>>(wv, bv, wq, bq, wk, bk);
    xprep_kernel   <<<dim3(NN / 32, BATCH), 256>>>(x);
    qkv_kernel     <<<dim3(NN / 128, BATCH), 320, GEMM_SM_TOTAL>>>();
    attn_kernel    <<<dim3(NN / TQ, BATCH), 256, SM_TOTAL>>>();
    final_kernel   <<<dim3(NN / 128, BATCH), 256, GEMM_SM_TOTAL>>>(x, bg, y);
}

// round 11
// speedup vs baseline: 1.7963x; 1.0166x over previous
#include <cuda_runtime.h>
#include <cuda_bf16.h>
#include <cstdint>

#define BATCH 4
#define CH    256
#define CQK   32
#define NN    4096

#define TQ     128
#define TJ     64
#define NTILES (NN / TJ)   // 64

// ---- unified KV tile (bf16 elements): [KH 64x40][KL 64x40][VH 256x64][VL 256x64]
#define KPAD       40
#define KV_TILE_EL 37888
#define KV_TILE_B  75776
#define KH_OFF     0
#define KL_OFF     5120
#define V_OFF      10240
#define SM_MB0  0
#define SM_MB1  8
#define SM_BUF  1024
#define SM_TOTAL (SM_BUF + 2 * KV_TILE_B)   // 152576

// GEMM kernels SMEM: [mbar pad 1024][B_hi 64KB][B_lo 64KB]
#define GEMM_SM_TOTAL (1024 + 2 * 65536)

// ---------------- scratch (device globals; no allocation allowed) ----------
__device__ __nv_bfloat16 g_qh[(size_t)BATCH * NN * CQK];
__device__ __nv_bfloat16 g_ql[(size_t)BATCH * NN * CQK];
__device__ __align__(128) __nv_bfloat16 g_kv[(size_t)BATCH * NTILES * KV_TILE_EL];
__device__ __align__(128) __nv_bfloat16 g_aoh[(size_t)BATCH * NN * CH];  // swizzled
__device__ __align__(128) __nv_bfloat16 g_aol[(size_t)BATCH * NN * CH];
__device__ __align__(128) __nv_bfloat16 g_xh[(size_t)BATCH * NN * CH];   // x^T swizzled
__device__ __align__(128) __nv_bfloat16 g_xl[(size_t)BATCH * NN * CH];
__device__ __nv_bfloat16 g_wgh[CH * CH];
__device__ __nv_bfloat16 g_wgl[CH * CH];
__device__ __nv_bfloat16 g_wh[320 * CH];   // [wv;wq;wk] hi
__device__ __nv_bfloat16 g_wl[320 * CH];
__device__ float         g_bqkv[320];

// ---------------- helpers ---------------------------------------------------
__device__ __forceinline__ unsigned cvt_bf16x2(float hi, float lo) {
    unsigned r;
    asm("cvt.rn.bf16x2.f32 %0, %1, %2;" : "=r"(r) : "f"(hi), "f"(lo));
    return r;
}
__device__ __forceinline__ float f_lo(unsigned u) { return __uint_as_float(u << 16); }
__device__ __forceinline__ float f_hi(unsigned u) { return __uint_as_float(u & 0xffff0000u); }

__device__ __forceinline__ uint32_t smem_u32(const void* p) {
    uint32_t a;
    asm("{ .reg .u64 t; cvta.to.shared.u64 t, %1; cvt.u32.u64 %0, t; }"
        : "=r"(a) : "l"(p));
    return a;
}

#define MBAR_INIT(addr, cnt) \
    asm volatile("mbarrier.init.shared.b64 [%0], %1;" :: "r"(addr), "r"(cnt) : "memory")
#define MBAR_EXPECT_TX(addr, bytes) \
    asm volatile("mbarrier.arrive.expect_tx.shared.b64 _, [%0], %1;" \
                 :: "r"(addr), "r"(bytes) : "memory")

__device__ __forceinline__ void mbar_wait(uint32_t addr, uint32_t parity) {
    asm volatile(
        "{\n\t.reg .pred P;\n\t"
        "WL_%=:\n\t"
        "mbarrier.try_wait.parity.acquire.cta.shared::cta.b64 P, [%0], %1, 0x989680;\n\t"
        "@P bra WD_%=;\n\t"
        "bra WL_%=;\n\t"
        "WD_%=:\n\t}"
        :: "r"(addr), "r"(parity) : "memory");
}
__device__ __forceinline__ void bulk_g2s(uint32_t dst, const void* src,
                                         uint32_t bytes, uint32_t mbar) {
    asm volatile(
        "cp.async.bulk.shared::cluster.global.mbarrier::complete_tx::bytes "
        "[%0], [%1], %2, [%3];"
        :: "r"(dst), "l"(src), "r"(bytes), "r"(mbar) : "memory");
}

__device__ __forceinline__ void ldsm4(unsigned& r0, unsigned& r1,
                                      unsigned& r2, unsigned& r3, uint32_t a) {
    asm volatile("ldmatrix.sync.aligned.m8n8.x4.shared.b16 {%0,%1,%2,%3}, [%4];"
                 : "=r"(r0), "=r"(r1), "=r"(r2), "=r"(r3) : "r"(a));
}

__device__ __forceinline__ void mma_bf16(float* d, const unsigned* a,
                                         unsigned b0, unsigned b1) {
    asm volatile(
        "mma.sync.aligned.m16n8k16.row.col.f32.bf16.bf16.f32 "
        "{%0,%1,%2,%3}, {%4,%5,%6,%7}, {%8,%9}, {%0,%1,%2,%3};"
        : "+f"(d[0]), "+f"(d[1]), "+f"(d[2]), "+f"(d[3])
        : "r"(a[0]), "r"(a[1]), "r"(a[2]), "r"(a[3]), "r"(b0), "r"(b1));
}

// load A fragments (weights) for k-slice ks
__device__ __forceinline__ void load_a_frags(
    unsigned ah[2][4], unsigned al[2][4],
    const __nv_bfloat16* wh, const __nv_bfloat16* wl,
    int c0, int g, int t, int ks)
{
#pragma unroll
    for (int mb = 0; mb < 2; mb++) {
        int cr  = c0 + mb * 16 + g;
        int col = ks * 16 + t * 2;
        ah[mb][0] = *(const unsigned*)(wh + cr * CH + col);
        ah[mb][1] = *(const unsigned*)(wh + (cr + 8) * CH + col);
        ah[mb][2] = *(const unsigned*)(wh + cr * CH + col + 8);
        ah[mb][3] = *(const unsigned*)(wh + (cr + 8) * CH + col + 8);
        al[mb][0] = *(const unsigned*)(wl + cr * CH + col);
        al[mb][1] = *(const unsigned*)(wl + (cr + 8) * CH + col);
        al[mb][2] = *(const unsigned*)(wl + cr * CH + col + 8);
        al[mb][3] = *(const unsigned*)(wl + (cr + 8) * CH + col + 8);
    }
}

// ============================================================================
// Kernel P0: wg -> bf16 hi/lo
// ============================================================================
__global__ void __launch_bounds__(256)
wgprep_kernel(const float* __restrict__ wg)
{
    int i = blockIdx.x * 256 + threadIdx.x;
    float a = wg[2 * i], b = wg[2 * i + 1];
    unsigned h = cvt_bf16x2(b, a);
    unsigned l = cvt_bf16x2(b - f_hi(h), a - f_lo(h));
    *(unsigned*)(g_wgh + 2 * i) = h;
    *(unsigned*)(g_wgl + 2 * i) = l;
}

// ============================================================================
// Kernel P1: stacked [wv;wq;wk] -> bf16 hi/lo + combined bias
// ============================================================================
__global__ void __launch_bounds__(256)
wqkvprep_kernel(const float* __restrict__ wv, const float* __restrict__ bv,
                const float* __restrict__ wq, const float* __restrict__ bq,
                const float* __restrict__ wk, const float* __restrict__ bk)
{
    int i = blockIdx.x * 256 + threadIdx.x;
    int row  = i >> 7;
    int col2 = (i & 127) * 2;
    const float* src = (row < 256) ? wv + row * CH
                     : (row < 288) ? wq + (row - 256) * CH
                                   : wk + (row - 288) * CH;
    float a = src[col2], b = src[col2 + 1];
    unsigned h = cvt_bf16x2(b, a);
    unsigned l = cvt_bf16x2(b - f_hi(h), a - f_lo(h));
    *(unsigned*)(g_wh + row * CH + col2) = h;
    *(unsigned*)(g_wl + row * CH + col2) = l;
    if (i < 320)
        g_bqkv[i] = (i < 256) ? bv[i] : (i < 288) ? bq[i - 256] : bk[i - 288];
}

// ============================================================================
// Kernel P2: x [b][c][n] fp32 -> x^T [b][n][c] bf16 hi/lo, ldmatrix-swizzled
// ============================================================================
__global__ void __launch_bounds__(256)
xprep_kernel(const float* __restrict__ x)
{
    __shared__ __align__(16) float xs[CH * 33];
    const int b   = blockIdx.y;
    const int n0  = blockIdx.x * 32;
    const int tid = threadIdx.x;

    const float* xb = x + (size_t)b * CH * NN + n0;
    for (int idx = tid; idx < CH * 32; idx += 256) {
        int c = idx >> 5, n = idx & 31;
        xs[c * 33 + n] = xb[(size_t)c * NN + n];
    }
    __syncthreads();

    const int n   = tid & 31;
    const int g3  = tid >> 5;
    const int nsw = (n0 + n) & 7;
    __nv_bfloat16* dh = g_xh + ((size_t)b * NN + n0 + n) * CH;
    __nv_bfloat16* dl = g_xl + ((size_t)b * NN + n0 + n) * CH;

#pragma unroll
    for (int cc = 0; cc < 4; cc++) {
        int ch = g3 * 4 + cc;
        float v[8];
#pragma unroll
        for (int j = 0; j < 8; j++) v[j] = xs[(ch * 8 + j) * 33 + n];
        unsigned h[4], l[4];
#pragma unroll
        for (int j = 0; j < 4; j++) {
            h[j] = cvt_bf16x2(v[2 * j + 1], v[2 * j]);
            l[j] = cvt_bf16x2(v[2 * j + 1] - f_hi(h[j]), v[2 * j] - f_lo(h[j]));
        }
        int mch = (ch ^ nsw) << 3;
        *(uint4*)(dh + mch) = make_uint4(h[0], h[1], h[2], h[3]);
        *(uint4*)(dl + mch) = make_uint4(l[0], l[1], l[2], l[3]);
    }
}

// ============================================================================
// Kernel P3: fused q/k/v projection via HMMA, A-frag prefetch pipeline.
// ============================================================================
__global__ void __launch_bounds__(320, 1)
qkv_kernel()
{
    extern __shared__ __align__(1024) char smem[];
    const uint32_t sb  = smem_u32(smem);
    const uint32_t mb0 = sb;

    const int tid  = threadIdx.x;
    const int w    = tid >> 5;
    const int lane = tid & 31;
    const int g    = lane >> 2;
    const int t    = lane & 3;
    const int b    = blockIdx.y;
    const int n0   = blockIdx.x * 128;
    const int c0   = w * 32;

    if (tid == 0) MBAR_INIT(mb0, 1);
    __syncthreads();
    if (tid == 0) {
        MBAR_EXPECT_TX(mb0, 131072);
        bulk_g2s(sb + 1024,         g_xh + ((size_t)b * NN + n0) * CH, 65536, mb0);
        bulk_g2s(sb + 1024 + 65536, g_xl + ((size_t)b * NN + n0) * CH, 65536, mb0);
    }

    float d[2][16][4];
#pragma unroll
    for (int mb = 0; mb < 2; mb++)
#pragma unroll
        for (int nb = 0; nb < 16; nb++) {
            d[mb][nb][0] = 0.f; d[mb][nb][1] = 0.f;
            d[mb][nb][2] = 0.f; d[mb][nb][3] = 0.f;
        }

    const uint32_t b_row = sb + 1024
        + (uint32_t)(((lane >> 4) * 8 + (lane & 7)) * 512);
    const int chsel = (lane >> 3) & 1;
    const int r7 = lane & 7;

    // prefetch ks=0 A-frags while waiting on B staging
    unsigned ah[2][2][4], al[2][2][4];
    load_a_frags(ah[0], al[0], g_wh, g_wl, c0, g, t, 0);

    mbar_wait(mb0, 0);
    __syncthreads();

#pragma unroll
    for (int ks = 0; ks < 16; ks++) {
        const int cur = ks & 1, nxt = cur ^ 1;
        if (ks < 15)
            load_a_frags(ah[nxt], al[nxt], g_wh, g_wl, c0, g, t, ks + 1);

        const uint32_t sw = (uint32_t)(((2 * ks + chsel) ^ r7) * 16);
#pragma unroll
        for (int p = 0; p < 8; p++) {
            uint32_t addr = b_row + (uint32_t)(p * 16 * 512) + sw;
            unsigned bh0, bh1, bh2, bh3, bl0, bl1, bl2, bl3;
            ldsm4(bh0, bh1, bh2, bh3, addr);
            ldsm4(bl0, bl1, bl2, bl3, addr + 65536);
#pragma unroll
            for (int mb = 0; mb < 2; mb++) {
                mma_bf16(d[mb][2 * p],     ah[cur][mb], bh0, bh1);
                mma_bf16(d[mb][2 * p],     ah[cur][mb], bl0, bl1);
                mma_bf16(d[mb][2 * p],     al[cur][mb], bh0, bh1);
                mma_bf16(d[mb][2 * p + 1], ah[cur][mb], bh2, bh3);
                mma_bf16(d[mb][2 * p + 1], ah[cur][mb], bl2, bl3);
                mma_bf16(d[mb][2 * p + 1], al[cur][mb], bh2, bh3);
            }
        }
    }

    // ---- epilogue: scatter to V (warps 0-7), q (warp 8), K (warp 9) ----
    const size_t kvbase = (size_t)b * NTILES * KV_TILE_EL;
#pragma unroll
    for (int mb = 0; mb < 2; mb++) {
        int rA = c0 + mb * 16 + g;
        int rB = rA + 8;
        float biasA = g_bqkv[rA], biasB = g_bqkv[rB];
#pragma unroll
        for (int nb = 0; nb < 16; nb++) {
            int n    = n0 + nb * 8 + t * 2;
            int tile = n >> 6;
            int jt   = n & 63;
            size_t kvb = kvbase + (size_t)tile * KV_TILE_EL;
            float vA0 = d[mb][nb][0] + biasA, vA1 = d[mb][nb][1] + biasA;
            float vB0 = d[mb][nb][2] + biasB, vB1 = d[mb][nb][3] + biasB;
            if (w < 8) {
                size_t vb = kvb + 5120;
                unsigned hA = cvt_bf16x2(vA1, vA0);
                unsigned lA = cvt_bf16x2(vA1 - f_hi(hA), vA0 - f_lo(hA));
                size_t offA = (size_t)rA * 64 + (((jt >> 3) ^ (rA & 7)) << 3) + (jt & 7);
                *(unsigned*)(g_kv + vb + offA)         = hA;
                *(unsigned*)(g_kv + vb + 16384 + offA) = lA;
                unsigned hB = cvt_bf16x2(vB1, vB0);
                unsigned lB = cvt_bf16x2(vB1 - f_hi(hB), vB0 - f_lo(hB));
                size_t offB = (size_t)rB * 64 + (((jt >> 3) ^ (rB & 7)) << 3) + (jt & 7);
                *(unsigned*)(g_kv + vb + offB)         = hB;
                *(unsigned*)(g_kv + vb + 16384 + offB) = lB;
            } else if (w == 8) {
                int dA = rA - 256, dB = rB - 256;
                size_t r0 = ((size_t)b * NN + n) * CQK;
                size_t r1 = r0 + CQK;
                __nv_bfloat16 hA0 = __float2bfloat16(vA0);
                __nv_bfloat16 hA1 = __float2bfloat16(vA1);
                g_qh[r0 + dA] = hA0; g_ql[r0 + dA] = __float2bfloat16(vA0 - __bfloat162float(hA0));
                g_qh[r1 + dA] = hA1; g_ql[r1 + dA] = __float2bfloat16(vA1 - __bfloat162float(hA1));
                __nv_bfloat16 hB0 = __float2bfloat16(vB0);
                __nv_bfloat16 hB1 = __float2bfloat16(vB1);
                g_qh[r0 + dB] = hB0; g_ql[r0 + dB] = __float2bfloat16(vB0 - __bfloat162float(hB0));
                g_qh[r1 + dB] = hB1; g_ql[r1 + dB] = __float2bfloat16(vB1 - __bfloat162float(hB1));
            } else {
                int dA = rA - 288, dB = rB - 288;
                size_t k0 = kvb + (size_t)jt * KPAD;
                size_t k1 = k0 + KPAD;
                __nv_bfloat16 hA0 = __float2bfloat16(vA0);
                __nv_bfloat16 hA1 = __float2bfloat16(vA1);
                g_kv[k0 + dA] = hA0; g_kv[k0 + 2560 + dA] = __float2bfloat16(vA0 - __bfloat162float(hA0));
                g_kv[k1 + dA] = hA1; g_kv[k1 + 2560 + dA] = __float2bfloat16(vA1 - __bfloat162float(hA1));
                __nv_bfloat16 hB0 = __float2bfloat16(vB0);
                __nv_bfloat16 hB1 = __float2bfloat16(vB1);
                g_kv[k0 + dB] = hB0; g_kv[k0 + 2560 + dB] = __float2bfloat16(vB0 - __bfloat162float(hB0));
                g_kv[k1 + dB] = hB1; g_kv[k1 + 2560 + dB] = __float2bfloat16(vB1 - __bfloat162float(hB1));
            }
        }
    }
}

// ============================================================================
// Kernel 3: HMMA flash attention (unchanged from R10)
// ============================================================================
__global__ void __launch_bounds__(256, 1)
attn_kernel()
{
    extern __shared__ __align__(1024) char smem[];

    const int tid  = threadIdx.x;
    const int w    = tid >> 5;
    const int lane = tid & 31;
    const int g    = lane >> 2;
    const int t    = lane & 3;
    const int b    = blockIdx.y;
    const int q0   = blockIdx.x * TQ;
    const int row0 = q0 + w * 16 + g;

    const uint32_t sb  = smem_u32(smem);
    const uint32_t mb0 = sb + SM_MB0;
    const uint32_t mb1 = sb + SM_MB1;

    if (tid == 0) { MBAR_INIT(mb0, 1); MBAR_INIT(mb1, 1); }
    __syncthreads();

    const __nv_bfloat16* kv_src = g_kv + (size_t)b * NTILES * KV_TILE_EL;

    const uint32_t k_lm = (uint32_t)(((lane & 7) * KPAD + (lane >> 3) * 8) * 2);
    const int vm = lane >> 3;
    const int vr = lane & 7;
    const uint32_t v_row = (uint32_t)(((vm >> 1) * 8 + vr) * 128);

    unsigned qh[2][4], ql[2][4];
    {
        const __nv_bfloat16* qhp = g_qh + (size_t)b * NN * CQK;
        const __nv_bfloat16* qlp = g_ql + (size_t)b * NN * CQK;
#pragma unroll
        for (int kq = 0; kq < 2; kq++) {
            int c0 = kq * 16 + t * 2;
            qh[kq][0] = *(const unsigned*)(qhp + (size_t)row0 * CQK + c0);
            qh[kq][1] = *(const unsigned*)(qhp + (size_t)(row0 + 8) * CQK + c0);
            qh[kq][2] = *(const unsigned*)(qhp + (size_t)row0 * CQK + c0 + 8);
            qh[kq][3] = *(const unsigned*)(qhp + (size_t)(row0 + 8) * CQK + c0 + 8);
            ql[kq][0] = *(const unsigned*)(qlp + (size_t)row0 * CQK + c0);
            ql[kq][1] = *(const unsigned*)(qlp + (size_t)(row0 + 8) * CQK + c0);
            ql[kq][2] = *(const unsigned*)(qlp + (size_t)row0 * CQK + c0 + 8);
            ql[kq][3] = *(const unsigned*)(qlp + (size_t)(row0 + 8) * CQK + c0 + 8);
        }
    }

    float o[32][4];
#pragma unroll
    for (int cb = 0; cb < 32; cb++) {
        o[cb][0] = 0.f; o[cb][1] = 0.f; o[cb][2] = 0.f; o[cb][3] = 0.f;
    }
    float rs0 = 0.f, rs1 = 0.f;

    if (tid == 0) {
        MBAR_EXPECT_TX(mb0, KV_TILE_B);
        bulk_g2s(sb + SM_BUF, kv_src, KV_TILE_B, mb0);
    }

    for (int tl = 0; tl < NTILES; tl++) {
        if (tl + 1 < NTILES && tid == 0) {
            uint32_t mb = ((tl + 1) & 1) ? mb1 : mb0;
            MBAR_EXPECT_TX(mb, KV_TILE_B);
            bulk_g2s(sb + SM_BUF + ((tl + 1) & 1) * KV_TILE_B,
                     kv_src + (size_t)(tl + 1) * KV_TILE_EL, KV_TILE_B, mb);
        }
        mbar_wait((tl & 1) ? mb1 : mb0, (tl >> 1) & 1);
        __syncthreads();

        const uint32_t bb  = sb + SM_BUF + (tl & 1) * KV_TILE_B;
        const uint32_t khb = bb + KH_OFF + k_lm;
        const uint32_t klb = bb + KL_OFF + k_lm;
        const uint32_t vhb = bb + V_OFF + v_row;
        const uint32_t vlb = vhb + 32768;

#pragma unroll
        for (int kb = 0; kb < 4; kb++) {
            const uint32_t vsw = (uint32_t)(((kb * 2 + (vm & 1)) ^ vr) * 16);

            float s0a[4] = {0.f, 0.f, 0.f, 0.f};
            float s0b[4] = {0.f, 0.f, 0.f, 0.f};
            float s1a[4] = {0.f, 0.f, 0.f, 0.f};
            float s1b[4] = {0.f, 0.f, 0.f, 0.f};
#pragma unroll
            for (int jbi = 0; jbi < 2; jbi++) {
                const uint32_t koff = (uint32_t)((kb * 2 + jbi) * 8 * KPAD * 2);
                unsigned kh0, kh1, kh2, kh3, kl0, kl1, kl2, kl3;
                ldsm4(kh0, kh1, kh2, kh3, khb + koff);
                ldsm4(kl0, kl1, kl2, kl3, klb + koff);
                float* sa = jbi ? s1a : s0a;
                float* sc = jbi ? s1b : s0b;
                mma_bf16(sa, qh[0], kh0, kh1);
                mma_bf16(sa, qh[0], kl0, kl1);
                mma_bf16(sa, ql[0], kh0, kh1);
                mma_bf16(sc, qh[1], kh2, kh3);
                mma_bf16(sc, qh[1], kl2, kl3);
                mma_bf16(sc, ql[1], kh2, kh3);
            }

            float e00 = __expf(s0a[0] + s0b[0]), e01 = __expf(s0a[1] + s0b[1]);
            float e02 = __expf(s0a[2] + s0b[2]), e03 = __expf(s0a[3] + s0b[3]);
            float e10 = __expf(s1a[0] + s1b[0]), e11 = __expf(s1a[1] + s1b[1]);
            float e12 = __expf(s1a[2] + s1b[2]), e13 = __expf(s1a[3] + s1b[3]);
            rs0 += e00 + e01 + e10 + e11;
            rs1 += e02 + e03 + e12 + e13;

            unsigned pa[4], pl[4];
            pa[0] = cvt_bf16x2(e01, e00);
            pa[1] = cvt_bf16x2(e03, e02);
            pa[2] = cvt_bf16x2(e11, e10);
            pa[3] = cvt_bf16x2(e13, e12);
            pl[0] = cvt_bf16x2(e01 - f_hi(pa[0]), e00 - f_lo(pa[0]));
            pl[1] = cvt_bf16x2(e03 - f_hi(pa[1]), e02 - f_lo(pa[1]));
            pl[2] = cvt_bf16x2(e11 - f_hi(pa[2]), e10 - f_lo(pa[2]));
            pl[3] = cvt_bf16x2(e13 - f_hi(pa[3]), e12 - f_lo(pa[3]));

            uint32_t avh = vhb + vsw;
            uint32_t avl = vlb + vsw;
#pragma unroll
            for (int p = 0; p < 16; p++) {
                unsigned vh0a, vh1a, vh0b, vh1b;
                unsigned vl0a, vl1a, vl0b, vl1b;
                ldsm4(vh0a, vh1a, vh0b, vh1b, avh);
                ldsm4(vl0a, vl1a, vl0b, vl1b, avl);
                mma_bf16(o[2 * p],     pa, vh0a, vh1a);
                mma_bf16(o[2 * p],     pa, vl0a, vl1a);
                mma_bf16(o[2 * p],     pl, vh0a, vh1a);
                mma_bf16(o[2 * p + 1], pa, vh0b, vh1b);
                mma_bf16(o[2 * p + 1], pa, vl0b, vl1b);
                mma_bf16(o[2 * p + 1], pl, vh0b, vh1b);
                avh += 16 * 128;
                avl += 16 * 128;
            }
        }
        __syncthreads();
    }

    rs0 += __shfl_xor_sync(0xffffffffu, rs0, 1);
    rs0 += __shfl_xor_sync(0xffffffffu, rs0, 2);
    rs1 += __shfl_xor_sync(0xffffffffu, rs1, 1);
    rs1 += __shfl_xor_sync(0xffffffffu, rs1, 2);
    const float inv0 = 1.0f / rs0;
    const float inv1 = 1.0f / rs1;

    const size_t r0b = ((size_t)b * NN + row0) * CH;
    const size_t r1b = ((size_t)b * NN + row0 + 8) * CH;
#pragma unroll
    for (int cb = 0; cb < 32; cb++) {
        size_t off = (size_t)(((cb ^ g) << 3) + t * 2);
        float v0 = o[cb][0] * inv0, v1 = o[cb][1] * inv0;
        unsigned h = cvt_bf16x2(v1, v0);
        unsigned l = cvt_bf16x2(v1 - f_hi(h), v0 - f_lo(h));
        *(unsigned*)(g_aoh + r0b + off) = h;
        *(unsigned*)(g_aol + r0b + off) = l;
        float u0 = o[cb][2] * inv1, u1 = o[cb][3] * inv1;
        unsigned h2 = cvt_bf16x2(u1, u0);
        unsigned l2 = cvt_bf16x2(u1 - f_hi(h2), u0 - f_lo(h2));
        *(unsigned*)(g_aoh + r1b + off) = h2;
        *(unsigned*)(g_aol + r1b + off) = l2;
    }
}

// ============================================================================
// Kernel 4: HMMA output projection + residual, A-frag prefetch pipeline.
// ============================================================================
__global__ void __launch_bounds__(256, 1)
final_kernel(const float* __restrict__ x,
             const float* __restrict__ bg,
             float* __restrict__ y)
{
    extern __shared__ __align__(1024) char smem[];
    const uint32_t sb  = smem_u32(smem);
    const uint32_t mb0 = sb;

    const int tid  = threadIdx.x;
    const int w    = tid >> 5;
    const int lane = tid & 31;
    const int g    = lane >> 2;
    const int t    = lane & 3;
    const int b    = blockIdx.y;
    const int n0   = blockIdx.x * 128;
    const int c0   = w * 32;

    if (tid == 0) MBAR_INIT(mb0, 1);
    __syncthreads();
    if (tid == 0) {
        MBAR_EXPECT_TX(mb0, 131072);
        bulk_g2s(sb + 1024,         g_aoh + ((size_t)b * NN + n0) * CH, 65536, mb0);
        bulk_g2s(sb + 1024 + 65536, g_aol + ((size_t)b * NN + n0) * CH, 65536, mb0);
    }

    float d[2][16][4];
#pragma unroll
    for (int mb = 0; mb < 2; mb++)
#pragma unroll
        for (int nb = 0; nb < 16; nb++) {
            d[mb][nb][0] = 0.f; d[mb][nb][1] = 0.f;
            d[mb][nb][2] = 0.f; d[mb][nb][3] = 0.f;
        }

    const uint32_t ao_row = sb + 1024
        + (uint32_t)(((lane >> 4) * 8 + (lane & 7)) * 512);
    const int chsel = (lane >> 3) & 1;
    const int r7 = lane & 7;

    unsigned ah[2][2][4], al[2][2][4];
    load_a_frags(ah[0], al[0], g_wgh, g_wgl, c0, g, t, 0);

    mbar_wait(mb0, 0);
    __syncthreads();

#pragma unroll
    for (int ks = 0; ks < 16; ks++) {
        const int cur = ks & 1, nxt = cur ^ 1;
        if (ks < 15)
            load_a_frags(ah[nxt], al[nxt], g_wgh, g_wgl, c0, g, t, ks + 1);

        const uint32_t sw = (uint32_t)((((2 * ks + chsel) ^ r7)) * 16);
#pragma unroll
        for (int p = 0; p < 8; p++) {
            uint32_t addr = ao_row + (uint32_t)(p * 16 * 512) + sw;
            unsigned bh0, bh1, bh2, bh3, bl0, bl1, bl2, bl3;
            ldsm4(bh0, bh1, bh2, bh3, addr);
            ldsm4(bl0, bl1, bl2, bl3, addr + 65536);
#pragma unroll
            for (int mb = 0; mb < 2; mb++) {
                mma_bf16(d[mb][2 * p],     ah[cur][mb], bh0, bh1);
                mma_bf16(d[mb][2 * p],     ah[cur][mb], bl0, bl1);
                mma_bf16(d[mb][2 * p],     al[cur][mb], bh0, bh1);
                mma_bf16(d[mb][2 * p + 1], ah[cur][mb], bh2, bh3);
                mma_bf16(d[mb][2 * p + 1], ah[cur][mb], bl2, bl3);
                mma_bf16(d[mb][2 * p + 1], al[cur][mb], bh2, bh3);
            }
        }
    }

#pragma unroll
    for (int mb = 0; mb < 2; mb++) {
        int cA = c0 + mb * 16 + g;
        int cB = cA + 8;
        float bgA = bg[cA], bgB = bg[cB];
        const float* xA = x + ((size_t)b * CH + cA) * NN + n0 + t * 2;
        const float* xB = x + ((size_t)b * CH + cB) * NN + n0 + t * 2;
        float* yA = y + ((size_t)b * CH + cA) * NN + n0 + t * 2;
        float* yB = y + ((size_t)b * CH + cB) * NN + n0 + t * 2;
#pragma unroll
        for (int nb = 0; nb < 16; nb++) {
            float2 xr = *(const float2*)(xA + nb * 8);
            *(float2*)(yA + nb * 8) =
                make_float2(xr.x + bgA + d[mb][nb][0],
                            xr.y + bgA + d[mb][nb][1]);
            float2 xs2 = *(const float2*)(xB + nb * 8);
            *(float2*)(yB + nb * 8) =
                make_float2(xs2.x + bgB + d[mb][nb][2],
                            xs2.y + bgB + d[mb][nb][3]);
        }
    }
}

// ============================================================================
extern "C" void kernel_launch(void* const* d_in, const int* in_sizes, int n_in,
                              void* d_out, int out_size)
{
    const float* x  = (const float*)d_in[0];
    const float* wq = (const float*)d_in[1];
    const float* bq = (const float*)d_in[2];
    const float* wk = (const float*)d_in[3];
    const float* bk = (const float*)d_in[4];
    const float* wv = (const float*)d_in[5];
    const float* bv = (const float*)d_in[6];
    const float* wg = (const float*)d_in[7];
    const float* bg = (const float*)d_in[8];
    float* y = (float*)d_out;

    cudaFuncSetAttribute(attn_kernel,
                         cudaFuncAttributeMaxDynamicSharedMemorySize, SM_TOTAL);
    cudaFuncSetAttribute(qkv_kernel,
                         cudaFuncAttributeMaxDynamicSharedMemorySize, GEMM_SM_TOTAL);
    cudaFuncSetAttribute(final_kernel,
                         cudaFuncAttributeMaxDynamicSharedMemorySize, GEMM_SM_TOTAL);

    wgprep_kernel  <<<CH * CH / 512, 256>>>(wg);
    wqkvprep_kernel<<<320 * CH / 512, 256>>>(wv, bv, wq, bq, wk, bk);
    xprep_kernel   <<<dim3(NN / 32, BATCH), 256>>>(x);
    qkv_kernel     <<<dim3(NN / 128, BATCH), 320, GEMM_SM_TOTAL>>>();
    attn_kernel    <<<dim3(NN / TQ, BATCH), 256, SM_TOTAL>>>();
    final_kernel   <<<dim3(NN / 128, BATCH), 256, GEMM_SM_TOTAL>>>(x, bg, y);
}